// round 2
// baseline (speedup 1.0000x reference)
#include <cuda_runtime.h>
#include <math.h>

#define BB 64
#define NN 512
#define VV 64
#define HH 512
#define RR 4
#define KK 32
#define EPSF 1e-8f

// output offsets (floats), tuple order:
// logits, value, h_new, c_new, mem_new, w_r, write_w, usage_new, link_new, prec_new
#define OUT_LOGITS 0
#define OUT_VALUE  1152
#define OUT_H      1216
#define OUT_C      33984
#define OUT_MEM    66752
#define OUT_WR     2163904
#define OUT_WW     2294976
#define OUT_USAGE  2327744
#define OUT_LINK   2360512
#define OUT_PREC   19137728

// workspace (device globals; no allocation allowed)
__device__ __align__(16) float g_ro[BB * 272];
__device__ __align__(16) float g_rpi[BB * RR * 3];
__device__ __align__(16) float g_memnorm[BB * NN];
__device__ __align__(16) float g_cw[BB * RR * NN];
__device__ __align__(16) float g_fw[BB * RR * NN];
__device__ __align__(16) float g_bw[BB * RR * NN];
__device__ __align__(16) float g_psi[BB * NN];
__device__ __align__(16) float g_rvec[BB * RR * VV];
__device__ __align__(16) float g_inT[896 * BB];
__device__ __align__(16) float g_gpart[4 * BB * 2048];
__device__ __align__(16) float g_wo[BB * 256];
__device__ __align__(16) float g_erase[BB * VV];
__device__ __align__(16) float g_add[BB * VV];
__device__ __align__(16) float g_wmisc[BB * 4];
__device__ __align__(16) float g_wsc[BB * NN];
__device__ __align__(16) float g_cww[BB * NN];
__device__ __align__(16) float g_alloc[BB * NN];

__device__ __forceinline__ float sigf(float x) { return 1.f / (1.f + expf(-x)); }
__device__ __forceinline__ float softplusf(float x) { return x > 20.f ? x : log1pf(expf(x)); }

// 1) ro = W_read @ h + b_read  (272 rows x 512 dot per batch)
__global__ void k_readproj(const float* __restrict__ Wr, const float* __restrict__ br,
                           const float* __restrict__ h) {
    int lane = threadIdx.x & 31;
    int row  = blockIdx.x * 8 + (threadIdx.x >> 5);   // 0..271 (grid.x=34)
    int b    = blockIdx.y * 32 + lane;                // 0..63 (grid.y=2)
    const float4* w4 = (const float4*)(Wr + row * HH);
    const float4* h4 = (const float4*)(h + b * HH);
    float acc = 0.f;
#pragma unroll 8
    for (int k = 0; k < HH / 4; k++) {
        float4 w = w4[k], v = h4[k];
        acc += w.x * v.x + w.y * v.y + w.z * v.z + w.w * v.w;
    }
    g_ro[b * 272 + row] = acc + br[row];
}

// 2) mem_norm[b,n]
__global__ void k_memnorm(const float* __restrict__ mem) {
    int lane = threadIdx.x & 31;
    int gid  = blockIdx.x * 8 + (threadIdx.x >> 5);   // 32768 rows
    const float2* p = (const float2*)(mem + (size_t)gid * VV);
    float2 v = p[lane];
    float s = v.x * v.x + v.y * v.y;
#pragma unroll
    for (int o = 16; o > 0; o >>= 1) s += __shfl_down_sync(0xffffffffu, s, o);
    if (lane == 0) g_memnorm[gid] = fmaxf(sqrtf(s), EPSF);
}

// 3) content read weights per (b,r): cosine sim, beta, top-K softmax; also rpi
__global__ void k_content(const float* __restrict__ mem) {
    int b = blockIdx.x, r = blockIdx.y, tid = threadIdx.x;
    __shared__ __align__(16) float key[64];
    __shared__ float s[512];
    __shared__ float s2[512];
    __shared__ float red[16];
    __shared__ float sh_beta, sh_kn, sh_tot;

    if (tid < 64) key[tid] = g_ro[b * 272 + r * 68 + tid];
    __syncthreads();
    if (tid == 0) {
        sh_beta = softplusf(g_ro[b * 272 + r * 68 + 64]);
        float p0 = g_ro[b * 272 + r * 68 + 65];
        float p1 = g_ro[b * 272 + r * 68 + 66];
        float p2 = g_ro[b * 272 + r * 68 + 67];
        float mx = fmaxf(p0, fmaxf(p1, p2));
        float e0 = expf(p0 - mx), e1 = expf(p1 - mx), e2 = expf(p2 - mx);
        float inv = 1.f / (e0 + e1 + e2);
        g_rpi[(b * 4 + r) * 3 + 0] = e0 * inv;
        g_rpi[(b * 4 + r) * 3 + 1] = e1 * inv;
        g_rpi[(b * 4 + r) * 3 + 2] = e2 * inv;
    }
    if (tid < 32) {
        float v = key[tid] * key[tid] + key[tid + 32] * key[tid + 32];
#pragma unroll
        for (int o = 16; o > 0; o >>= 1) v += __shfl_down_sync(0xffffffffu, v, o);
        if (tid == 0) sh_kn = fmaxf(sqrtf(v), EPSF);
    }
    __syncthreads();

    const float4* mrow = (const float4*)(mem + ((size_t)b * NN + tid) * VV);
    float acc = 0.f;
#pragma unroll
    for (int i = 0; i < 16; i++) {
        float4 m4 = mrow[i];
        acc += m4.x * key[4 * i] + m4.y * key[4 * i + 1] + m4.z * key[4 * i + 2] + m4.w * key[4 * i + 3];
    }
    float score = sh_beta * acc / (g_memnorm[b * NN + tid] * sh_kn);
    s[tid] = score;
    s2[tid] = score;
    __syncthreads();

    // bitonic ascending sort (512)
    for (int k = 2; k <= 512; k <<= 1)
        for (int j = k >> 1; j > 0; j >>= 1) {
            int ixj = tid ^ j;
            if (ixj > tid) {
                float a = s2[tid], c = s2[ixj];
                bool up = ((tid & k) == 0);
                if ((a > c) == up) { s2[tid] = c; s2[ixj] = a; }
            }
            __syncthreads();
        }

    float kth = s2[512 - KK];
    float mx = s2[511];
    float e = (s[tid] >= kth) ? expf(s[tid] - mx) : 0.f;

    float v = e;
    int lane = tid & 31, wid = tid >> 5;
#pragma unroll
    for (int o = 16; o > 0; o >>= 1) v += __shfl_down_sync(0xffffffffu, v, o);
    if (lane == 0) red[wid] = v;
    __syncthreads();
    if (tid == 0) {
        float t = 0.f;
#pragma unroll
        for (int i = 0; i < 16; i++) t += red[i];
        sh_tot = t;
    }
    __syncthreads();
    g_cw[(b * 4 + r) * 512 + tid] = e / sh_tot;
}

// 4) fw[b,r,n] = sum_m link[b,n,m] * rw[b,r,m]
__global__ void k_fw(const float* __restrict__ link, const float* __restrict__ rw) {
    __shared__ float srw[2048];
    int b = blockIdx.x;
    for (int i = threadIdx.x; i < 2048; i += 256) srw[i] = rw[b * 2048 + i];
    __syncthreads();
    int lane = threadIdx.x & 31;
    int n = blockIdx.y * 8 + (threadIdx.x >> 5);
    const float4* lrow = (const float4*)(link + ((size_t)b * NN + n) * NN);
    float a0 = 0.f, a1 = 0.f, a2 = 0.f, a3 = 0.f;
    for (int mq = lane; mq < 128; mq += 32) {
        float4 l = lrow[mq];
        int m = mq * 4;
        a0 += l.x * srw[m]        + l.y * srw[m + 1]    + l.z * srw[m + 2]    + l.w * srw[m + 3];
        a1 += l.x * srw[512 + m]  + l.y * srw[513 + m]  + l.z * srw[514 + m]  + l.w * srw[515 + m];
        a2 += l.x * srw[1024 + m] + l.y * srw[1025 + m] + l.z * srw[1026 + m] + l.w * srw[1027 + m];
        a3 += l.x * srw[1536 + m] + l.y * srw[1537 + m] + l.z * srw[1538 + m] + l.w * srw[1539 + m];
    }
#pragma unroll
    for (int o = 16; o > 0; o >>= 1) {
        a0 += __shfl_down_sync(0xffffffffu, a0, o);
        a1 += __shfl_down_sync(0xffffffffu, a1, o);
        a2 += __shfl_down_sync(0xffffffffu, a2, o);
        a3 += __shfl_down_sync(0xffffffffu, a3, o);
    }
    if (lane == 0) {
        g_fw[(b * 4 + 0) * 512 + n] = a0;
        g_fw[(b * 4 + 1) * 512 + n] = a1;
        g_fw[(b * 4 + 2) * 512 + n] = a2;
        g_fw[(b * 4 + 3) * 512 + n] = a3;
    }
}

// 5) bw[b,r,n] = sum_m link[b,m,n] * rw[b,r,m]
__global__ void k_bw(const float* __restrict__ link, const float* __restrict__ rw) {
    __shared__ float srw[2048];
    int b = blockIdx.y;
    for (int i = threadIdx.x; i < 2048; i += 128) srw[i] = rw[b * 2048 + i];
    __syncthreads();
    int n = blockIdx.x * 128 + threadIdx.x;
    const float* lp = link + (size_t)b * NN * NN + n;
    float a0 = 0.f, a1 = 0.f, a2 = 0.f, a3 = 0.f;
#pragma unroll 4
    for (int m = 0; m < 512; m++) {
        float l = lp[(size_t)m * 512];
        a0 += l * srw[m];
        a1 += l * srw[512 + m];
        a2 += l * srw[1024 + m];
        a3 += l * srw[1536 + m];
    }
    g_bw[(b * 4 + 0) * 512 + n] = a0;
    g_bw[(b * 4 + 1) * 512 + n] = a1;
    g_bw[(b * 4 + 2) * 512 + n] = a2;
    g_bw[(b * 4 + 3) * 512 + n] = a3;
}

// 6) w_r mix + psi
__global__ void k_wrpsi(float* __restrict__ out) {
    int gid = blockIdx.x * 256 + threadIdx.x;  // < 32768
    int b = gid >> 9, n = gid & 511;
    float psi = 1.f;
#pragma unroll
    for (int r = 0; r < 4; r++) {
        int o = (b * 4 + r) * 512 + n;
        float p0 = g_rpi[(b * 4 + r) * 3 + 0];
        float p1 = g_rpi[(b * 4 + r) * 3 + 1];
        float p2 = g_rpi[(b * 4 + r) * 3 + 2];
        float wr = p0 * g_bw[o] + p1 * g_cw[o] + p2 * g_fw[o];
        out[OUT_WR + o] = wr;
        psi *= (1.f - wr);
    }
    g_psi[gid] = psi;
}

// 7) rvec[b,r,v] = sum_n w_r[b,r,n] * memory[b,n,v]
__global__ void k_rvec(const float* __restrict__ mem, const float* __restrict__ out) {
    int b = blockIdx.x;
    int r = threadIdx.x >> 6, v = threadIdx.x & 63;
    const float* wr = out + OUT_WR + (b * 4 + r) * 512;
    const float* mp = mem + (size_t)b * NN * VV + v;
    float acc = 0.f;
#pragma unroll 4
    for (int n = 0; n < 512; n++) acc += wr[n] * mp[(size_t)n * 64];
    g_rvec[b * 256 + r * 64 + v] = acc;
}

// 8) pack transposed input inT[k][b]: x(128) | rvec(256) | h(512)
__global__ void k_pack(const float* __restrict__ x, const float* __restrict__ h) {
    int gid = blockIdx.x * 256 + threadIdx.x;  // < 57344
    int k = gid >> 6, b = gid & 63;
    float v;
    if (k < 128) v = x[b * 128 + k];
    else if (k < 384) v = g_rvec[b * 256 + (k - 128)];
    else v = h[b * 512 + (k - 384)];
    g_inT[k * 64 + b] = v;
}

// 9) gates GEMM: (64 x 2048), K=896 split into 4 partials
__global__ void k_gates(const float* __restrict__ Wih, const float* __restrict__ Whh) {
    __shared__ __align__(16) float Wt[16][68];
    __shared__ __align__(16) float It[16][68];
    int tid = threadIdx.x;
    int ks = blockIdx.y;
    int koff = (ks < 2) ? ks * 192 : 384 + (ks - 2) * 256;
    int klen = (ks < 2) ? 192 : 256;
    int j0 = blockIdx.x * 64;
    int tx = tid & 15, ty = tid >> 4;
    float acc[4][4];
#pragma unroll
    for (int i = 0; i < 4; i++)
#pragma unroll
        for (int j = 0; j < 4; j++) acc[i][j] = 0.f;
    int jj = tid >> 2, kq = tid & 3;
    for (int kst = 0; kst < klen; kst += 16) {
        int vk = koff + kst + kq * 4;
        const float* wp = (vk < 384) ? (Wih + (j0 + jj) * 384 + vk)
                                     : (Whh + (j0 + jj) * 512 + (vk - 384));
        float4 wv = *(const float4*)wp;
        Wt[kq * 4 + 0][jj] = wv.x;
        Wt[kq * 4 + 1][jj] = wv.y;
        Wt[kq * 4 + 2][jj] = wv.z;
        Wt[kq * 4 + 3][jj] = wv.w;
        *(float4*)&It[ty][tx * 4] = *(const float4*)&g_inT[(koff + kst + ty) * 64 + tx * 4];
        __syncthreads();
#pragma unroll
        for (int kk = 0; kk < 16; kk++) {
            float4 av = *(float4*)&It[kk][tx * 4];
            float4 wv2 = *(float4*)&Wt[kk][ty * 4];
            acc[0][0] += wv2.x * av.x; acc[0][1] += wv2.x * av.y; acc[0][2] += wv2.x * av.z; acc[0][3] += wv2.x * av.w;
            acc[1][0] += wv2.y * av.x; acc[1][1] += wv2.y * av.y; acc[1][2] += wv2.y * av.z; acc[1][3] += wv2.y * av.w;
            acc[2][0] += wv2.z * av.x; acc[2][1] += wv2.z * av.y; acc[2][2] += wv2.z * av.z; acc[2][3] += wv2.z * av.w;
            acc[3][0] += wv2.w * av.x; acc[3][1] += wv2.w * av.y; acc[3][2] += wv2.w * av.z; acc[3][3] += wv2.w * av.w;
        }
        __syncthreads();
    }
#pragma unroll
    for (int jq = 0; jq < 4; jq++)
#pragma unroll
        for (int bq = 0; bq < 4; bq++)
            g_gpart[(((size_t)ks * 64 + (tx * 4 + bq)) * 2048) + j0 + ty * 4 + jq] = acc[jq][bq];
}

// 10) LSTM activations
__global__ void k_lstm(const float* __restrict__ c, const float* __restrict__ bih,
                       const float* __restrict__ bhh, float* __restrict__ out) {
    int gid = blockIdx.x * 256 + threadIdx.x;  // < 32768
    int b = gid >> 9, hh = gid & 511;
    float gi = bih[hh] + bhh[hh];
    float gf = bih[512 + hh] + bhh[512 + hh];
    float gg = bih[1024 + hh] + bhh[1024 + hh];
    float go = bih[1536 + hh] + bhh[1536 + hh];
#pragma unroll
    for (int ks = 0; ks < 4; ks++) {
        const float* gp = g_gpart + ((size_t)(ks * 64 + b) * 2048);
        gi += gp[hh];
        gf += gp[512 + hh];
        gg += gp[1024 + hh];
        go += gp[1536 + hh];
    }
    float cn = sigf(gf) * c[gid] + sigf(gi) * tanhf(gg);
    float hn = sigf(go) * tanhf(cn);
    out[OUT_C + gid] = cn;
    out[OUT_H + gid] = hn;
}

// 11) output projections: wo(195), logits(18), value(1)
__global__ void k_outproj(const float* __restrict__ Ww, const float* __restrict__ bw_,
                          const float* __restrict__ Wp, const float* __restrict__ bp,
                          const float* __restrict__ Wv, const float* __restrict__ bv,
                          const float* __restrict__ out_h, float* __restrict__ out) {
    int lane = threadIdx.x & 31;
    int row = blockIdx.x * 8 + (threadIdx.x >> 5);
    if (row >= 214) return;
    int b = blockIdx.y * 32 + lane;
    const float* wrow;
    float bias;
    if (row < 195)      { wrow = Ww + row * 512;         bias = bw_[row]; }
    else if (row < 213) { wrow = Wp + (row - 195) * 512; bias = bp[row - 195]; }
    else                { wrow = Wv;                     bias = bv[0]; }
    const float4* w4 = (const float4*)wrow;
    const float4* h4 = (const float4*)(out_h + b * 512);
    float acc = bias;
#pragma unroll 8
    for (int k = 0; k < 128; k++) {
        float4 w = w4[k], v = h4[k];
        acc += w.x * v.x + w.y * v.y + w.z * v.z + w.w * v.w;
    }
    if (row < 195)      g_wo[b * 256 + row] = acc;
    else if (row < 213) out[OUT_LOGITS + b * 18 + (row - 195)] = acc;
    else                out[OUT_VALUE + b] = acc;
}

// 12) write prep
__global__ void k_wprep() {
    int b = blockIdx.x, v = threadIdx.x;
    __shared__ float part[2];
    float kv = g_wo[b * 256 + v];
    g_erase[b * 64 + v] = sigf(g_wo[b * 256 + 64 + v]);
    g_add[b * 64 + v] = tanhf(g_wo[b * 256 + 128 + v]);
    float s = kv * kv;
#pragma unroll
    for (int o = 16; o > 0; o >>= 1) s += __shfl_down_sync(0xffffffffu, s, o);
    if ((v & 31) == 0) part[v >> 5] = s;
    __syncthreads();
    if (v == 0) {
        g_wmisc[b * 4 + 3] = fmaxf(sqrtf(part[0] + part[1]), EPSF);
        g_wmisc[b * 4 + 0] = softplusf(g_wo[b * 256 + 192]);
        g_wmisc[b * 4 + 1] = sigf(g_wo[b * 256 + 193]);
        g_wmisc[b * 4 + 2] = sigf(g_wo[b * 256 + 194]);
    }
}

// 13) write content scores
__global__ void k_wsim(const float* __restrict__ mem) {
    int lane = threadIdx.x & 31;
    int gid = blockIdx.x * 8 + (threadIdx.x >> 5);  // b*512+n
    int b = gid >> 9;
    const float2* mp = (const float2*)(mem + (size_t)gid * 64);
    const float2* kp = (const float2*)(g_wo + b * 256);
    float2 m2 = mp[lane], k2 = kp[lane];
    float s = m2.x * k2.x + m2.y * k2.y;
#pragma unroll
    for (int o = 16; o > 0; o >>= 1) s += __shfl_down_sync(0xffffffffu, s, o);
    if (lane == 0)
        g_wsc[gid] = g_wmisc[b * 4 + 0] * s / (g_memnorm[gid] * g_wmisc[b * 4 + 3]);
}

// 14) write content softmax over N
__global__ void k_wsoftmax() {
    int b = blockIdx.x, tid = threadIdx.x;
    __shared__ float red[16];
    __shared__ float shm, shs;
    int lane = tid & 31, wid = tid >> 5;
    float s = g_wsc[b * 512 + tid];
    float v = s;
#pragma unroll
    for (int o = 16; o > 0; o >>= 1) v = fmaxf(v, __shfl_down_sync(0xffffffffu, v, o));
    if (lane == 0) red[wid] = v;
    __syncthreads();
    if (tid == 0) {
        float m = red[0];
#pragma unroll
        for (int i = 1; i < 16; i++) m = fmaxf(m, red[i]);
        shm = m;
    }
    __syncthreads();
    float e = expf(s - shm);
    v = e;
#pragma unroll
    for (int o = 16; o > 0; o >>= 1) v += __shfl_down_sync(0xffffffffu, v, o);
    if (lane == 0) red[wid] = v;
    __syncthreads();
    if (tid == 0) {
        float t = 0.f;
#pragma unroll
        for (int i = 0; i < 16; i++) t += red[i];
        shs = t;
    }
    __syncthreads();
    g_cww[b * 512 + tid] = e / shs;
}

// 15) allocation weighting
__global__ void k_alloc(const float* __restrict__ usage) {
    int b = blockIdx.x, tid = threadIdx.x;
    __shared__ float sv[512];
    __shared__ int si[512];
    __shared__ float sp[512];
    sv[tid] = usage[b * 512 + tid];
    si[tid] = tid;
    __syncthreads();
    for (int k = 2; k <= 512; k <<= 1)
        for (int j = k >> 1; j > 0; j >>= 1) {
            int ixj = tid ^ j;
            if (ixj > tid) {
                float a = sv[tid], c = sv[ixj];
                bool up = ((tid & k) == 0);
                if ((a > c) == up) {
                    sv[tid] = c; sv[ixj] = a;
                    int t = si[tid]; si[tid] = si[ixj]; si[ixj] = t;
                }
            }
            __syncthreads();
        }
    sp[tid] = sv[tid];
    __syncthreads();
    for (int off = 1; off < 512; off <<= 1) {
        float t = (tid >= off) ? sp[tid - off] : 1.f;
        __syncthreads();
        sp[tid] *= t;
        __syncthreads();
    }
    float excl = (tid == 0) ? 1.f : sp[tid - 1];
    g_alloc[b * 512 + si[tid]] = (1.f - sv[tid]) * excl;
}

// 16) write_w, prec_new, usage_new
__global__ void k_writew(const float* __restrict__ usage, const float* __restrict__ wwin,
                         const float* __restrict__ prec, float* __restrict__ out) {
    int b = blockIdx.x, tid = threadIdx.x;
    __shared__ float red[16];
    __shared__ float shws;
    int lane = tid & 31, wid = tid >> 5;
    float ga = g_wmisc[b * 4 + 1], gw = g_wmisc[b * 4 + 2];
    float ww = gw * (ga * g_alloc[b * 512 + tid] + (1.f - ga) * g_cww[b * 512 + tid]);
    out[OUT_WW + b * 512 + tid] = ww;
    float v = ww;
#pragma unroll
    for (int o = 16; o > 0; o >>= 1) v += __shfl_down_sync(0xffffffffu, v, o);
    if (lane == 0) red[wid] = v;
    __syncthreads();
    if (tid == 0) {
        float t = 0.f;
#pragma unroll
        for (int i = 0; i < 16; i++) t += red[i];
        shws = t;
    }
    __syncthreads();
    out[OUT_PREC + b * 512 + tid] = (1.f - shws) * prec[b * 512 + tid] + ww;
    float u = usage[b * 512 + tid], w0 = wwin[b * 512 + tid];
    out[OUT_USAGE + b * 512 + tid] = (u + w0 - u * w0) * g_psi[b * 512 + tid];
}

// 17) memory update
__global__ void k_memup(const float* __restrict__ mem, float* __restrict__ out) {
    int gid = blockIdx.x * 256 + threadIdx.x;  // < 524288 float4s
    int v4 = gid & 15, n = (gid >> 4) & 511, b = gid >> 13;
    float4 m = ((const float4*)mem)[gid];
    float ww = out[OUT_WW + b * 512 + n];
    float4 er = ((const float4*)g_erase)[b * 16 + v4];
    float4 ad = ((const float4*)g_add)[b * 16 + v4];
    float4 r;
    r.x = m.x * (1.f - ww * er.x) + ww * ad.x;
    r.y = m.y * (1.f - ww * er.y) + ww * ad.y;
    r.z = m.z * (1.f - ww * er.z) + ww * ad.z;
    r.w = m.w * (1.f - ww * er.w) + ww * ad.w;
    ((float4*)(out + OUT_MEM))[gid] = r;
}

// 18) link matrix update
__global__ void k_link(const float* __restrict__ link, const float* __restrict__ prec,
                       float* __restrict__ out) {
    int gid = blockIdx.x * 256 + threadIdx.x;  // < 4194304 float4s
    int mq = gid & 127, n = (gid >> 7) & 511, b = gid >> 16;
    float4 l = ((const float4*)link)[gid];
    float wn = out[OUT_WW + b * 512 + n];
    float4 wm = ((const float4*)(out + OUT_WW + b * 512))[mq];
    float4 p = ((const float4*)(prec + b * 512))[mq];
    float om = 1.f - wn;
    float4 r;
    r.x = om * (1.f - wm.x) * l.x + wn * p.x;
    r.y = om * (1.f - wm.y) * l.y + wn * p.y;
    r.z = om * (1.f - wm.z) * l.z + wn * p.z;
    r.w = om * (1.f - wm.w) * l.w + wn * p.w;
    int m0 = mq * 4;
    if (m0 == n)     r.x = 0.f;
    if (m0 + 1 == n) r.y = 0.f;
    if (m0 + 2 == n) r.z = 0.f;
    if (m0 + 3 == n) r.w = 0.f;
    ((float4*)(out + OUT_LINK))[gid] = r;
}

extern "C" void kernel_launch(void* const* d_in, const int* in_sizes, int n_in,
                              void* d_out, int out_size) {
    const float* x             = (const float*)d_in[0];
    const float* h             = (const float*)d_in[1];
    const float* c             = (const float*)d_in[2];
    const float* memory        = (const float*)d_in[3];
    const float* read_weights  = (const float*)d_in[4];
    const float* write_weights = (const float*)d_in[5];
    const float* usage         = (const float*)d_in[6];
    const float* link          = (const float*)d_in[7];
    const float* prec          = (const float*)d_in[8];
    const float* W_ih          = (const float*)d_in[9];
    const float* W_hh          = (const float*)d_in[10];
    const float* b_ih          = (const float*)d_in[11];
    const float* b_hh          = (const float*)d_in[12];
    const float* W_read        = (const float*)d_in[13];
    const float* b_read        = (const float*)d_in[14];
    const float* W_write       = (const float*)d_in[15];
    const float* b_write       = (const float*)d_in[16];
    const float* W_pol         = (const float*)d_in[17];
    const float* b_pol         = (const float*)d_in[18];
    const float* W_val         = (const float*)d_in[19];
    const float* b_val         = (const float*)d_in[20];
    float* out = (float*)d_out;

    k_readproj<<<dim3(34, 2), 256>>>(W_read, b_read, h);
    k_memnorm<<<4096, 256>>>(memory);
    k_content<<<dim3(64, 4), 512>>>(memory);
    k_fw<<<dim3(64, 64), 256>>>(link, read_weights);
    k_bw<<<dim3(4, 64), 128>>>(link, read_weights);
    k_wrpsi<<<128, 256>>>(out);
    k_rvec<<<64, 256>>>(memory, out);
    k_pack<<<224, 256>>>(x, h);
    k_gates<<<dim3(32, 4), 256>>>(W_ih, W_hh);
    k_lstm<<<128, 256>>>(c, b_ih, b_hh, out);
    k_outproj<<<dim3(27, 2), 256>>>(W_write, b_write, W_pol, b_pol, W_val, b_val, out + OUT_H, out);
    k_wprep<<<64, 64>>>();
    k_wsim<<<4096, 256>>>(memory);
    k_wsoftmax<<<64, 512>>>();
    k_alloc<<<64, 512>>>(usage);
    k_writew<<<64, 512>>>(usage, write_weights, prec, out);
    k_memup<<<2048, 256>>>(memory, out);
    k_link<<<16384, 256>>>(link, prec, out);
}

// round 3
// speedup vs baseline: 1.4186x; 1.4186x over previous
#include <cuda_runtime.h>
#include <math.h>

#define BB 64
#define NN 512
#define VV 64
#define HH 512
#define RR 4
#define KK 32
#define EPSF 1e-8f

// output offsets (floats), tuple order:
// logits, value, h_new, c_new, mem_new, w_r, write_w, usage_new, link_new, prec_new
#define OUT_LOGITS 0
#define OUT_VALUE  1152
#define OUT_H      1216
#define OUT_C      33984
#define OUT_MEM    66752
#define OUT_WR     2163904
#define OUT_WW     2294976
#define OUT_USAGE  2327744
#define OUT_LINK   2360512
#define OUT_PREC   19137728

// workspace
__device__ __align__(16) float g_ro[BB * 272];
__device__ __align__(16) float g_rpi[BB * RR * 3];
__device__ __align__(16) float g_memnorm[BB * NN];
__device__ __align__(16) float g_cw[BB * RR * NN];
__device__ __align__(16) float g_fw[BB * RR * NN];
__device__ __align__(16) float g_bwp[4 * BB * RR * NN];   // 4 m-chunk partials
__device__ __align__(16) float g_psi[BB * NN];
__device__ __align__(16) float g_inT[896 * BB];
__device__ __align__(16) float g_gpart[4 * BB * 2048];
__device__ __align__(16) float g_wo[BB * 256];
__device__ __align__(16) float g_erase[BB * VV];
__device__ __align__(16) float g_add[BB * VV];

__device__ __forceinline__ float sigf(float x) { return 1.f / (1.f + expf(-x)); }
__device__ __forceinline__ float softplusf(float x) { return x > 20.f ? x : log1pf(expf(x)); }

// ============================================================
// 1) fused: readproj (blocks 0..67) + memnorm (blocks 68..4163)
// ============================================================
__global__ void k_pre(const float* __restrict__ Wr, const float* __restrict__ br,
                      const float* __restrict__ h, const float* __restrict__ mem) {
    int lane = threadIdx.x & 31;
    int warp = threadIdx.x >> 5;
    if (blockIdx.x < 68) {
        int rp = blockIdx.x;
        int row = (rp % 34) * 8 + warp;          // 0..271
        int b   = (rp / 34) * 32 + lane;         // 0..63
        const float4* w4 = (const float4*)(Wr + row * HH);
        const float4* h4 = (const float4*)(h + b * HH);
        float acc = 0.f;
#pragma unroll 8
        for (int k = 0; k < HH / 4; k++) {
            float4 w = w4[k], v = h4[k];
            acc += w.x * v.x + w.y * v.y + w.z * v.z + w.w * v.w;
        }
        g_ro[b * 272 + row] = acc + br[row];
    } else {
        int gid = (blockIdx.x - 68) * 8 + warp;  // 32768 rows
        const float2* p = (const float2*)(mem + (size_t)gid * VV);
        float2 v = p[lane];
        float s = v.x * v.x + v.y * v.y;
#pragma unroll
        for (int o = 16; o > 0; o >>= 1) s += __shfl_down_sync(0xffffffffu, s, o);
        if (lane == 0) g_memnorm[gid] = fmaxf(sqrtf(s), EPSF);
    }
}

// ============================================================
// 2) content read weights per (b,r)
// ============================================================
__global__ void k_content(const float* __restrict__ mem) {
    int b = blockIdx.x, r = blockIdx.y, tid = threadIdx.x;
    __shared__ __align__(16) float key[64];
    __shared__ float s[512];
    __shared__ float s2[512];
    __shared__ float red[16];
    __shared__ float sh_beta, sh_kn, sh_tot;

    if (tid < 64) key[tid] = g_ro[b * 272 + r * 68 + tid];
    __syncthreads();
    if (tid == 0) {
        sh_beta = softplusf(g_ro[b * 272 + r * 68 + 64]);
        float p0 = g_ro[b * 272 + r * 68 + 65];
        float p1 = g_ro[b * 272 + r * 68 + 66];
        float p2 = g_ro[b * 272 + r * 68 + 67];
        float mx = fmaxf(p0, fmaxf(p1, p2));
        float e0 = expf(p0 - mx), e1 = expf(p1 - mx), e2 = expf(p2 - mx);
        float inv = 1.f / (e0 + e1 + e2);
        g_rpi[(b * 4 + r) * 3 + 0] = e0 * inv;
        g_rpi[(b * 4 + r) * 3 + 1] = e1 * inv;
        g_rpi[(b * 4 + r) * 3 + 2] = e2 * inv;
    }
    if (tid < 32) {
        float v = key[tid] * key[tid] + key[tid + 32] * key[tid + 32];
#pragma unroll
        for (int o = 16; o > 0; o >>= 1) v += __shfl_down_sync(0xffffffffu, v, o);
        if (tid == 0) sh_kn = fmaxf(sqrtf(v), EPSF);
    }
    __syncthreads();

    const float4* mrow = (const float4*)(mem + ((size_t)b * NN + tid) * VV);
    float acc = 0.f;
#pragma unroll
    for (int i = 0; i < 16; i++) {
        float4 m4 = mrow[i];
        acc += m4.x * key[4 * i] + m4.y * key[4 * i + 1] + m4.z * key[4 * i + 2] + m4.w * key[4 * i + 3];
    }
    float score = sh_beta * acc / (g_memnorm[b * NN + tid] * sh_kn);
    s[tid] = score;
    s2[tid] = score;
    __syncthreads();

    for (int k = 2; k <= 512; k <<= 1)
        for (int j = k >> 1; j > 0; j >>= 1) {
            int ixj = tid ^ j;
            if (ixj > tid) {
                float a = s2[tid], c = s2[ixj];
                bool up = ((tid & k) == 0);
                if ((a > c) == up) { s2[tid] = c; s2[ixj] = a; }
            }
            __syncthreads();
        }

    float kth = s2[512 - KK];
    float mx = s2[511];
    float e = (s[tid] >= kth) ? expf(s[tid] - mx) : 0.f;

    float v = e;
    int lane = tid & 31, wid = tid >> 5;
#pragma unroll
    for (int o = 16; o > 0; o >>= 1) v += __shfl_down_sync(0xffffffffu, v, o);
    if (lane == 0) red[wid] = v;
    __syncthreads();
    if (tid == 0) {
        float t = 0.f;
#pragma unroll
        for (int i = 0; i < 16; i++) t += red[i];
        sh_tot = t;
    }
    __syncthreads();
    g_cw[(b * 4 + r) * 512 + tid] = e / sh_tot;
}

// ============================================================
// 3) fw[b,r,n] = sum_m link[b,n,m] * rw[b,r,m]  (float4 smem loads)
// ============================================================
__global__ void k_fw(const float* __restrict__ link, const float* __restrict__ rw) {
    __shared__ __align__(16) float srw[2048];
    int b = blockIdx.x;
    for (int i = threadIdx.x; i < 512; i += 256)
        ((float4*)srw)[i] = ((const float4*)(rw + b * 2048))[i];
    __syncthreads();
    int lane = threadIdx.x & 31;
    int n = blockIdx.y * 8 + (threadIdx.x >> 5);
    const float4* lrow = (const float4*)(link + ((size_t)b * NN + n) * NN);
    float a0 = 0.f, a1 = 0.f, a2 = 0.f, a3 = 0.f;
#pragma unroll
    for (int i = 0; i < 4; i++) {
        int mq = lane + 32 * i;
        float4 l = lrow[mq];
        float4 w0 = *(const float4*)&srw[mq * 4];
        float4 w1 = *(const float4*)&srw[512 + mq * 4];
        float4 w2 = *(const float4*)&srw[1024 + mq * 4];
        float4 w3 = *(const float4*)&srw[1536 + mq * 4];
        a0 += l.x * w0.x + l.y * w0.y + l.z * w0.z + l.w * w0.w;
        a1 += l.x * w1.x + l.y * w1.y + l.z * w1.z + l.w * w1.w;
        a2 += l.x * w2.x + l.y * w2.y + l.z * w2.z + l.w * w2.w;
        a3 += l.x * w3.x + l.y * w3.y + l.z * w3.z + l.w * w3.w;
    }
#pragma unroll
    for (int o = 16; o > 0; o >>= 1) {
        a0 += __shfl_down_sync(0xffffffffu, a0, o);
        a1 += __shfl_down_sync(0xffffffffu, a1, o);
        a2 += __shfl_down_sync(0xffffffffu, a2, o);
        a3 += __shfl_down_sync(0xffffffffu, a3, o);
    }
    if (lane == 0) {
        g_fw[(b * 4 + 0) * 512 + n] = a0;
        g_fw[(b * 4 + 1) * 512 + n] = a1;
        g_fw[(b * 4 + 2) * 512 + n] = a2;
        g_fw[(b * 4 + 3) * 512 + n] = a3;
    }
}

// ============================================================
// 4) bw partials: g_bwp[mc][b][r][n] = sum_{m in chunk} link[b,m,n]*rw[b,r,m]
//    grid (2, 64, 4), block 256
// ============================================================
__global__ void k_bw(const float* __restrict__ link, const float* __restrict__ rw) {
    __shared__ float srw[4][128];
    int b = blockIdx.y, mc = blockIdx.z;
    for (int i = threadIdx.x; i < 512; i += 256)
        srw[i >> 7][i & 127] = rw[b * 2048 + (i >> 7) * 512 + mc * 128 + (i & 127)];
    __syncthreads();
    int n = blockIdx.x * 256 + threadIdx.x;
    const float* lp = link + ((size_t)b * NN + mc * 128) * NN + n;
    float a0 = 0.f, a1 = 0.f, a2 = 0.f, a3 = 0.f;
#pragma unroll 8
    for (int m = 0; m < 128; m++) {
        float l = lp[(size_t)m * 512];
        a0 += l * srw[0][m];
        a1 += l * srw[1][m];
        a2 += l * srw[2][m];
        a3 += l * srw[3][m];
    }
    size_t base = (((size_t)mc * 64 + b) * 4) * 512 + n;
    g_bwp[base]           = a0;
    g_bwp[base + 512]     = a1;
    g_bwp[base + 1024]    = a2;
    g_bwp[base + 1536]    = a3;
}

// ============================================================
// 5) fused per-b: w_r mix + psi + rvec + pack inT
// ============================================================
__global__ void k_mix(const float* __restrict__ mem, const float* __restrict__ x,
                      const float* __restrict__ h, float* __restrict__ out) {
    int b = blockIdx.x, tid = threadIdx.x;  // 512 threads
    __shared__ float swr[4][512];
    __shared__ float sred[512];
    __shared__ float srv[256];
    int n = tid;
    float psi = 1.f;
#pragma unroll
    for (int r = 0; r < 4; r++) {
        int o = (b * 4 + r) * 512 + n;
        float bwv = g_bwp[((size_t)(0 * 64 + b) * 4 + r) * 512 + n]
                  + g_bwp[((size_t)(1 * 64 + b) * 4 + r) * 512 + n]
                  + g_bwp[((size_t)(2 * 64 + b) * 4 + r) * 512 + n]
                  + g_bwp[((size_t)(3 * 64 + b) * 4 + r) * 512 + n];
        float p0 = g_rpi[(b * 4 + r) * 3 + 0];
        float p1 = g_rpi[(b * 4 + r) * 3 + 1];
        float p2 = g_rpi[(b * 4 + r) * 3 + 2];
        float wr = p0 * bwv + p1 * g_cw[o] + p2 * g_fw[o];
        swr[r][n] = wr;
        out[OUT_WR + o] = wr;
        psi *= (1.f - wr);
    }
    g_psi[b * 512 + n] = psi;
    __syncthreads();

    // rvec: two halves of n range
    int half = tid >> 8;
    int r = (tid >> 6) & 3;
    int v = tid & 63;
    const float* mp = mem + (size_t)b * NN * VV + v;
    float acc = 0.f;
#pragma unroll 4
    for (int nn = half * 256; nn < half * 256 + 256; nn++)
        acc += swr[r][nn] * mp[(size_t)nn * 64];
    sred[tid] = acc;
    __syncthreads();
    if (tid < 256) srv[tid] = sred[tid] + sred[tid + 256];
    __syncthreads();

    // pack inT[k][b]: x(128) | rvec(256) | h(512)
    for (int k = tid; k < 896; k += 512) {
        float val;
        if (k < 128) val = x[b * 128 + k];
        else if (k < 384) val = srv[k - 128];
        else val = h[b * 512 + (k - 384)];
        g_inT[k * 64 + b] = val;
    }
}

// ============================================================
// 6) gates GEMM: (64 x 2048), K=896 split into 4 partials
// ============================================================
__global__ void k_gates(const float* __restrict__ Wih, const float* __restrict__ Whh) {
    __shared__ __align__(16) float Wt[16][68];
    __shared__ __align__(16) float It[16][68];
    int tid = threadIdx.x;
    int ks = blockIdx.y;
    int koff = (ks < 2) ? ks * 192 : 384 + (ks - 2) * 256;
    int klen = (ks < 2) ? 192 : 256;
    int j0 = blockIdx.x * 64;
    int tx = tid & 15, ty = tid >> 4;
    float acc[4][4];
#pragma unroll
    for (int i = 0; i < 4; i++)
#pragma unroll
        for (int j = 0; j < 4; j++) acc[i][j] = 0.f;
    int jj = tid >> 2, kq = tid & 3;
    for (int kst = 0; kst < klen; kst += 16) {
        int vk = koff + kst + kq * 4;
        const float* wp = (vk < 384) ? (Wih + (j0 + jj) * 384 + vk)
                                     : (Whh + (j0 + jj) * 512 + (vk - 384));
        float4 wv = *(const float4*)wp;
        Wt[kq * 4 + 0][jj] = wv.x;
        Wt[kq * 4 + 1][jj] = wv.y;
        Wt[kq * 4 + 2][jj] = wv.z;
        Wt[kq * 4 + 3][jj] = wv.w;
        *(float4*)&It[ty][tx * 4] = *(const float4*)&g_inT[(koff + kst + ty) * 64 + tx * 4];
        __syncthreads();
#pragma unroll
        for (int kk = 0; kk < 16; kk++) {
            float4 av = *(float4*)&It[kk][tx * 4];
            float4 wv2 = *(float4*)&Wt[kk][ty * 4];
            acc[0][0] += wv2.x * av.x; acc[0][1] += wv2.x * av.y; acc[0][2] += wv2.x * av.z; acc[0][3] += wv2.x * av.w;
            acc[1][0] += wv2.y * av.x; acc[1][1] += wv2.y * av.y; acc[1][2] += wv2.y * av.z; acc[1][3] += wv2.y * av.w;
            acc[2][0] += wv2.z * av.x; acc[2][1] += wv2.z * av.y; acc[2][2] += wv2.z * av.z; acc[2][3] += wv2.z * av.w;
            acc[3][0] += wv2.w * av.x; acc[3][1] += wv2.w * av.y; acc[3][2] += wv2.w * av.z; acc[3][3] += wv2.w * av.w;
        }
        __syncthreads();
    }
#pragma unroll
    for (int jq = 0; jq < 4; jq++)
#pragma unroll
        for (int bq = 0; bq < 4; bq++)
            g_gpart[(((size_t)ks * 64 + (tx * 4 + bq)) * 2048) + j0 + ty * 4 + jq] = acc[jq][bq];
}

// ============================================================
// 7) LSTM activations
// ============================================================
__global__ void k_lstm(const float* __restrict__ c, const float* __restrict__ bih,
                       const float* __restrict__ bhh, float* __restrict__ out) {
    int gid = blockIdx.x * 256 + threadIdx.x;  // < 32768
    int b = gid >> 9, hh = gid & 511;
    float gi = bih[hh] + bhh[hh];
    float gf = bih[512 + hh] + bhh[512 + hh];
    float gg = bih[1024 + hh] + bhh[1024 + hh];
    float go = bih[1536 + hh] + bhh[1536 + hh];
#pragma unroll
    for (int ks = 0; ks < 4; ks++) {
        const float* gp = g_gpart + ((size_t)(ks * 64 + b) * 2048);
        gi += gp[hh];
        gf += gp[512 + hh];
        gg += gp[1024 + hh];
        go += gp[1536 + hh];
    }
    float cn = sigf(gf) * c[gid] + sigf(gi) * tanhf(gg);
    float hn = sigf(go) * tanhf(cn);
    out[OUT_C + gid] = cn;
    out[OUT_H + gid] = hn;
}

// ============================================================
// 8) output projections: wo(195), logits(18), value(1)
// ============================================================
__global__ void k_outproj(const float* __restrict__ Ww, const float* __restrict__ bw_,
                          const float* __restrict__ Wp, const float* __restrict__ bp,
                          const float* __restrict__ Wv, const float* __restrict__ bv,
                          const float* __restrict__ out_h, float* __restrict__ out) {
    int lane = threadIdx.x & 31;
    int row = blockIdx.x * 8 + (threadIdx.x >> 5);
    if (row >= 214) return;
    int b = blockIdx.y * 32 + lane;
    const float* wrow;
    float bias;
    if (row < 195)      { wrow = Ww + row * 512;         bias = bw_[row]; }
    else if (row < 213) { wrow = Wp + (row - 195) * 512; bias = bp[row - 195]; }
    else                { wrow = Wv;                     bias = bv[0]; }
    const float4* w4 = (const float4*)wrow;
    const float4* h4 = (const float4*)(out_h + b * 512);
    float acc = bias;
#pragma unroll 8
    for (int k = 0; k < 128; k++) {
        float4 w = w4[k], v = h4[k];
        acc += w.x * v.x + w.y * v.y + w.z * v.z + w.w * v.w;
    }
    if (row < 195)      g_wo[b * 256 + row] = acc;
    else if (row < 213) out[OUT_LOGITS + b * 18 + (row - 195)] = acc;
    else                out[OUT_VALUE + b] = acc;
}

// ============================================================
// 9) fused per-b write path: wprep + wsim + softmax + alloc + writew
// ============================================================
__global__ void k_wall(const float* __restrict__ mem, const float* __restrict__ usage,
                       const float* __restrict__ wwin, const float* __restrict__ prec,
                       float* __restrict__ out) {
    int b = blockIdx.x, tid = threadIdx.x;  // 512 threads
    __shared__ __align__(16) float skey[64];
    __shared__ float part[2];
    __shared__ float salloc[512];
    __shared__ float sv[512];
    __shared__ float sp[512];
    __shared__ int si[512];
    __shared__ float red[16];
    __shared__ float s_beta, s_knorm, s_ga, s_gw, s_m, s_sum, s_ws;
    int lane = tid & 31, wid = tid >> 5;

    if (tid < 64) {
        float kv = g_wo[b * 256 + tid];
        skey[tid] = kv;
        g_erase[b * 64 + tid] = sigf(g_wo[b * 256 + 64 + tid]);
        g_add[b * 64 + tid] = tanhf(g_wo[b * 256 + 128 + tid]);
        float s = kv * kv;
#pragma unroll
        for (int o = 16; o > 0; o >>= 1) s += __shfl_down_sync(0xffffffffu, s, o);
        if (lane == 0) part[tid >> 5] = s;
    }
    __syncthreads();
    if (tid == 0) {
        s_knorm = fmaxf(sqrtf(part[0] + part[1]), EPSF);
        s_beta = softplusf(g_wo[b * 256 + 192]);
        s_ga = sigf(g_wo[b * 256 + 193]);
        s_gw = sigf(g_wo[b * 256 + 194]);
    }
    __syncthreads();

    // wsim for n = tid
    const float4* mrow = (const float4*)(mem + ((size_t)b * NN + tid) * VV);
    float acc = 0.f;
#pragma unroll
    for (int i = 0; i < 16; i++) {
        float4 m4 = mrow[i];
        acc += m4.x * skey[4 * i] + m4.y * skey[4 * i + 1] + m4.z * skey[4 * i + 2] + m4.w * skey[4 * i + 3];
    }
    float sim = s_beta * acc / (g_memnorm[b * NN + tid] * s_knorm);

    // softmax over the 512 sims
    float v = sim;
#pragma unroll
    for (int o = 16; o > 0; o >>= 1) v = fmaxf(v, __shfl_down_sync(0xffffffffu, v, o));
    if (lane == 0) red[wid] = v;
    __syncthreads();
    if (tid == 0) {
        float m = red[0];
#pragma unroll
        for (int i = 1; i < 16; i++) m = fmaxf(m, red[i]);
        s_m = m;
    }
    __syncthreads();
    float e = expf(sim - s_m);
    v = e;
#pragma unroll
    for (int o = 16; o > 0; o >>= 1) v += __shfl_down_sync(0xffffffffu, v, o);
    if (lane == 0) red[wid] = v;
    __syncthreads();
    if (tid == 0) {
        float t = 0.f;
#pragma unroll
        for (int i = 0; i < 16; i++) t += red[i];
        s_sum = t;
    }
    __syncthreads();
    float cww = e / s_sum;

    // allocation: bitonic sort usage + product scan + unsort
    sv[tid] = usage[b * 512 + tid];
    si[tid] = tid;
    __syncthreads();
    for (int k = 2; k <= 512; k <<= 1)
        for (int j = k >> 1; j > 0; j >>= 1) {
            int ixj = tid ^ j;
            if (ixj > tid) {
                float a = sv[tid], c = sv[ixj];
                bool up = ((tid & k) == 0);
                if ((a > c) == up) {
                    sv[tid] = c; sv[ixj] = a;
                    int t = si[tid]; si[tid] = si[ixj]; si[ixj] = t;
                }
            }
            __syncthreads();
        }
    sp[tid] = sv[tid];
    __syncthreads();
    for (int off = 1; off < 512; off <<= 1) {
        float t = (tid >= off) ? sp[tid - off] : 1.f;
        __syncthreads();
        sp[tid] *= t;
        __syncthreads();
    }
    float excl = (tid == 0) ? 1.f : sp[tid - 1];
    salloc[si[tid]] = (1.f - sv[tid]) * excl;
    __syncthreads();

    // write_w, ws, prec_new, usage_new
    float ww = s_gw * (s_ga * salloc[tid] + (1.f - s_ga) * cww);
    out[OUT_WW + b * 512 + tid] = ww;
    v = ww;
#pragma unroll
    for (int o = 16; o > 0; o >>= 1) v += __shfl_down_sync(0xffffffffu, v, o);
    if (lane == 0) red[wid] = v;
    __syncthreads();
    if (tid == 0) {
        float t = 0.f;
#pragma unroll
        for (int i = 0; i < 16; i++) t += red[i];
        s_ws = t;
    }
    __syncthreads();
    out[OUT_PREC + b * 512 + tid] = (1.f - s_ws) * prec[b * 512 + tid] + ww;
    float u = usage[b * 512 + tid], w0 = wwin[b * 512 + tid];
    out[OUT_USAGE + b * 512 + tid] = (u + w0 - u * w0) * g_psi[b * 512 + tid];
}

// ============================================================
// 10) fused memory + link update
// ============================================================
__global__ void k_memlink(const float* __restrict__ mem, const float* __restrict__ link,
                          const float* __restrict__ prec, float* __restrict__ out) {
    int bx = blockIdx.x;
    if (bx < 2048) {
        int gid = bx * 256 + threadIdx.x;  // < 524288 float4s
        int v4 = gid & 15, n = (gid >> 4) & 511, b = gid >> 13;
        float4 m = ((const float4*)mem)[gid];
        float ww = out[OUT_WW + b * 512 + n];
        float4 er = ((const float4*)g_erase)[b * 16 + v4];
        float4 ad = ((const float4*)g_add)[b * 16 + v4];
        float4 r;
        r.x = m.x * (1.f - ww * er.x) + ww * ad.x;
        r.y = m.y * (1.f - ww * er.y) + ww * ad.y;
        r.z = m.z * (1.f - ww * er.z) + ww * ad.z;
        r.w = m.w * (1.f - ww * er.w) + ww * ad.w;
        ((float4*)(out + OUT_MEM))[gid] = r;
    } else {
        int gid = (bx - 2048) * 256 + threadIdx.x;  // < 4194304 float4s
        int mq = gid & 127, n = (gid >> 7) & 511, b = gid >> 16;
        float4 l = ((const float4*)link)[gid];
        float wn = out[OUT_WW + b * 512 + n];
        float4 wm = ((const float4*)(out + OUT_WW + b * 512))[mq];
        float4 p = ((const float4*)(prec + b * 512))[mq];
        float om = 1.f - wn;
        float4 r;
        r.x = om * (1.f - wm.x) * l.x + wn * p.x;
        r.y = om * (1.f - wm.y) * l.y + wn * p.y;
        r.z = om * (1.f - wm.z) * l.z + wn * p.z;
        r.w = om * (1.f - wm.w) * l.w + wn * p.w;
        int m0 = mq * 4;
        if (m0 == n)     r.x = 0.f;
        if (m0 + 1 == n) r.y = 0.f;
        if (m0 + 2 == n) r.z = 0.f;
        if (m0 + 3 == n) r.w = 0.f;
        ((float4*)(out + OUT_LINK))[gid] = r;
    }
}

extern "C" void kernel_launch(void* const* d_in, const int* in_sizes, int n_in,
                              void* d_out, int out_size) {
    const float* x             = (const float*)d_in[0];
    const float* h             = (const float*)d_in[1];
    const float* c             = (const float*)d_in[2];
    const float* memory        = (const float*)d_in[3];
    const float* read_weights  = (const float*)d_in[4];
    const float* write_weights = (const float*)d_in[5];
    const float* usage         = (const float*)d_in[6];
    const float* link          = (const float*)d_in[7];
    const float* prec          = (const float*)d_in[8];
    const float* W_ih          = (const float*)d_in[9];
    const float* W_hh          = (const float*)d_in[10];
    const float* b_ih          = (const float*)d_in[11];
    const float* b_hh          = (const float*)d_in[12];
    const float* W_read        = (const float*)d_in[13];
    const float* b_read        = (const float*)d_in[14];
    const float* W_write       = (const float*)d_in[15];
    const float* b_write       = (const float*)d_in[16];
    const float* W_pol         = (const float*)d_in[17];
    const float* b_pol         = (const float*)d_in[18];
    const float* W_val         = (const float*)d_in[19];
    const float* b_val         = (const float*)d_in[20];
    float* out = (float*)d_out;

    k_pre<<<4164, 256>>>(W_read, b_read, h, memory);
    k_content<<<dim3(64, 4), 512>>>(memory);
    k_fw<<<dim3(64, 64), 256>>>(link, read_weights);
    k_bw<<<dim3(2, 64, 4), 256>>>(link, read_weights);
    k_mix<<<64, 512>>>(memory, x, h, out);
    k_gates<<<dim3(32, 4), 256>>>(W_ih, W_hh);
    k_lstm<<<128, 256>>>(c, b_ih, b_hh, out);
    k_outproj<<<dim3(27, 2), 256>>>(W_write, b_write, W_pol, b_pol, W_val, b_val, out + OUT_H, out);
    k_wall<<<64, 512>>>(memory, usage, write_weights, prec, out);
    k_memlink<<<18432, 256>>>(memory, link, prec, out);
}

// round 4
// speedup vs baseline: 1.5333x; 1.0808x over previous
#include <cuda_runtime.h>
#include <math.h>

#define BB 64
#define NN 512
#define VV 64
#define HH 512
#define RR 4
#define KK 32
#define EPSF 1e-8f

// output offsets (floats), tuple order:
// logits, value, h_new, c_new, mem_new, w_r, write_w, usage_new, link_new, prec_new
#define OUT_LOGITS 0
#define OUT_VALUE  1152
#define OUT_H      1216
#define OUT_C      33984
#define OUT_MEM    66752
#define OUT_WR     2163904
#define OUT_WW     2294976
#define OUT_USAGE  2327744
#define OUT_LINK   2360512
#define OUT_PREC   19137728

// workspace
__device__ __align__(16) float g_ro[BB * 272];
__device__ __align__(16) float g_rpi[BB * RR * 3];
__device__ __align__(16) float g_memnorm[BB * NN];
__device__ __align__(16) float g_cw[BB * RR * NN];
__device__ __align__(16) float g_fw[BB * RR * NN];
__device__ __align__(16) float g_bwp[8 * BB * RR * NN];   // 8 m-chunk partials
__device__ __align__(16) float g_psi[BB * NN];
__device__ __align__(16) float g_inT[896 * BB];
__device__ __align__(16) float g_gpart[4 * BB * 2048];
__device__ __align__(16) float g_wo[BB * 256];
__device__ __align__(16) float g_erase[BB * VV];
__device__ __align__(16) float g_add[BB * VV];

__device__ __forceinline__ float sigf(float x) { return 1.f / (1.f + expf(-x)); }
__device__ __forceinline__ float softplusf(float x) { return x > 20.f ? x : log1pf(expf(x)); }

// ============================================================
// 1) fused: readproj (blocks 0..67) + memnorm (blocks 68..4163)
// ============================================================
__global__ void k_pre(const float* __restrict__ Wr, const float* __restrict__ br,
                      const float* __restrict__ h, const float* __restrict__ mem) {
    int lane = threadIdx.x & 31;
    int warp = threadIdx.x >> 5;
    if (blockIdx.x < 68) {
        int rp = blockIdx.x;
        int row = (rp % 34) * 8 + warp;          // 0..271
        int b   = (rp / 34) * 32 + lane;         // 0..63
        const float4* w4 = (const float4*)(Wr + row * HH);
        const float4* h4 = (const float4*)(h + b * HH);
        float acc = 0.f;
#pragma unroll 8
        for (int k = 0; k < HH / 4; k++) {
            float4 w = w4[k], v = h4[k];
            acc += w.x * v.x + w.y * v.y + w.z * v.z + w.w * v.w;
        }
        g_ro[b * 272 + row] = acc + br[row];
    } else {
        int gid = (blockIdx.x - 68) * 8 + warp;  // 32768 rows
        const float2* p = (const float2*)(mem + (size_t)gid * VV);
        float2 v = p[lane];
        float s = v.x * v.x + v.y * v.y;
#pragma unroll
        for (int o = 16; o > 0; o >>= 1) s += __shfl_down_sync(0xffffffffu, s, o);
        if (lane == 0) g_memnorm[gid] = fmaxf(sqrtf(s), EPSF);
    }
}

// ============================================================
// 2) mega-kernel: content (256 blocks) + fw (2048 blocks) + bw (512 blocks)
//    512 threads per block
// ============================================================
__global__ void __launch_bounds__(512) k_big(const float* __restrict__ mem,
                                             const float* __restrict__ link,
                                             const float* __restrict__ rw) {
    __shared__ __align__(16) float buf[2080];
    int tid = threadIdx.x;
    int blk = blockIdx.x;

    if (blk < 2048) {
        // ---------------- fw: 16 rows per block ----------------
        int b = blk >> 5, chunk = blk & 31;
        for (int i = tid; i < 512; i += 512)
            ((float4*)buf)[i] = ((const float4*)(rw + b * 2048))[i];
        __syncthreads();
        int lane = tid & 31;
        int n = chunk * 16 + (tid >> 5);
        const float4* lrow = (const float4*)(link + ((size_t)b * NN + n) * NN);
        float a0 = 0.f, a1 = 0.f, a2 = 0.f, a3 = 0.f;
#pragma unroll
        for (int i = 0; i < 4; i++) {
            int mq = lane + 32 * i;
            float4 l = lrow[mq];
            float4 w0 = *(const float4*)&buf[mq * 4];
            float4 w1 = *(const float4*)&buf[512 + mq * 4];
            float4 w2 = *(const float4*)&buf[1024 + mq * 4];
            float4 w3 = *(const float4*)&buf[1536 + mq * 4];
            a0 += l.x * w0.x + l.y * w0.y + l.z * w0.z + l.w * w0.w;
            a1 += l.x * w1.x + l.y * w1.y + l.z * w1.z + l.w * w1.w;
            a2 += l.x * w2.x + l.y * w2.y + l.z * w2.z + l.w * w2.w;
            a3 += l.x * w3.x + l.y * w3.y + l.z * w3.z + l.w * w3.w;
        }
#pragma unroll
        for (int o = 16; o > 0; o >>= 1) {
            a0 += __shfl_down_sync(0xffffffffu, a0, o);
            a1 += __shfl_down_sync(0xffffffffu, a1, o);
            a2 += __shfl_down_sync(0xffffffffu, a2, o);
            a3 += __shfl_down_sync(0xffffffffu, a3, o);
        }
        if (lane == 0) {
            g_fw[(b * 4 + 0) * 512 + n] = a0;
            g_fw[(b * 4 + 1) * 512 + n] = a1;
            g_fw[(b * 4 + 2) * 512 + n] = a2;
            g_fw[(b * 4 + 3) * 512 + n] = a3;
        }
    } else if (blk < 2560) {
        // ---------------- bw partial: 64 rows (chunk mc), all 512 cols ----------------
        int idx = blk - 2048;
        int b = idx >> 3, mc = idx & 7;
        if (tid < 256)
            buf[tid] = rw[b * 2048 + (tid >> 6) * 512 + mc * 64 + (tid & 63)];
        __syncthreads();
        int n = tid;
        const float* lp = link + ((size_t)b * NN + mc * 64) * NN + n;
        float a0 = 0.f, a1 = 0.f, a2 = 0.f, a3 = 0.f;
#pragma unroll 8
        for (int m = 0; m < 64; m++) {
            float l = lp[(size_t)m * 512];
            a0 += l * buf[m];
            a1 += l * buf[64 + m];
            a2 += l * buf[128 + m];
            a3 += l * buf[192 + m];
        }
        size_t base = (((size_t)mc * 64 + b) * 4) * 512 + n;
        g_bwp[base]        = a0;
        g_bwp[base + 512]  = a1;
        g_bwp[base + 1024] = a2;
        g_bwp[base + 1536] = a3;
    } else {
        // ---------------- content: per (b,r) ----------------
        int idx = blk - 2560;
        int b = idx >> 2, r = idx & 3;
        float* key = buf;             // 64
        float* s   = buf + 64;        // 512
        float* s2  = buf + 576;       // 512
        float* red = buf + 1088;      // 16
        float* sc  = buf + 1104;      // beta, kn, tot
        int lane = tid & 31, wid = tid >> 5;

        if (tid < 64) key[tid] = g_ro[b * 272 + r * 68 + tid];
        __syncthreads();
        if (tid == 0) {
            sc[0] = softplusf(g_ro[b * 272 + r * 68 + 64]);
            float p0 = g_ro[b * 272 + r * 68 + 65];
            float p1 = g_ro[b * 272 + r * 68 + 66];
            float p2 = g_ro[b * 272 + r * 68 + 67];
            float mx = fmaxf(p0, fmaxf(p1, p2));
            float e0 = expf(p0 - mx), e1 = expf(p1 - mx), e2 = expf(p2 - mx);
            float inv = 1.f / (e0 + e1 + e2);
            g_rpi[(b * 4 + r) * 3 + 0] = e0 * inv;
            g_rpi[(b * 4 + r) * 3 + 1] = e1 * inv;
            g_rpi[(b * 4 + r) * 3 + 2] = e2 * inv;
        }
        if (tid < 32) {
            float v = key[tid] * key[tid] + key[tid + 32] * key[tid + 32];
#pragma unroll
            for (int o = 16; o > 0; o >>= 1) v += __shfl_down_sync(0xffffffffu, v, o);
            if (tid == 0) sc[1] = fmaxf(sqrtf(v), EPSF);
        }
        __syncthreads();

        const float4* mrow = (const float4*)(mem + ((size_t)b * NN + tid) * VV);
        float acc = 0.f;
#pragma unroll
        for (int i = 0; i < 16; i++) {
            float4 m4 = mrow[i];
            acc += m4.x * key[4 * i] + m4.y * key[4 * i + 1] + m4.z * key[4 * i + 2] + m4.w * key[4 * i + 3];
        }
        float score = sc[0] * acc / (g_memnorm[b * NN + tid] * sc[1]);
        s[tid] = score;
        s2[tid] = score;
        __syncthreads();

        for (int k = 2; k <= 512; k <<= 1)
            for (int j = k >> 1; j > 0; j >>= 1) {
                int ixj = tid ^ j;
                if (ixj > tid) {
                    float a = s2[tid], c = s2[ixj];
                    bool up = ((tid & k) == 0);
                    if ((a > c) == up) { s2[tid] = c; s2[ixj] = a; }
                }
                __syncthreads();
            }

        float kth = s2[512 - KK];
        float mx = s2[511];
        float e = (s[tid] >= kth) ? expf(s[tid] - mx) : 0.f;

        float v = e;
#pragma unroll
        for (int o = 16; o > 0; o >>= 1) v += __shfl_down_sync(0xffffffffu, v, o);
        if (lane == 0) red[wid] = v;
        __syncthreads();
        if (tid == 0) {
            float t = 0.f;
#pragma unroll
            for (int i = 0; i < 16; i++) t += red[i];
            sc[2] = t;
        }
        __syncthreads();
        g_cw[(b * 4 + r) * 512 + tid] = e / sc[2];
    }
}

// ============================================================
// 3) fused per-b: w_r mix + psi + rvec + pack inT
// ============================================================
__global__ void k_mix(const float* __restrict__ mem, const float* __restrict__ x,
                      const float* __restrict__ h, float* __restrict__ out) {
    int b = blockIdx.x, tid = threadIdx.x;  // 512 threads
    __shared__ float swr[4][512];
    __shared__ float sred[512];
    __shared__ float srv[256];
    int n = tid;
    float psi = 1.f;
#pragma unroll
    for (int r = 0; r < 4; r++) {
        int o = (b * 4 + r) * 512 + n;
        float bwv = 0.f;
#pragma unroll
        for (int mc = 0; mc < 8; mc++)
            bwv += g_bwp[((size_t)(mc * 64 + b) * 4 + r) * 512 + n];
        float p0 = g_rpi[(b * 4 + r) * 3 + 0];
        float p1 = g_rpi[(b * 4 + r) * 3 + 1];
        float p2 = g_rpi[(b * 4 + r) * 3 + 2];
        float wr = p0 * bwv + p1 * g_cw[o] + p2 * g_fw[o];
        swr[r][n] = wr;
        out[OUT_WR + o] = wr;
        psi *= (1.f - wr);
    }
    g_psi[b * 512 + n] = psi;
    __syncthreads();

    int half = tid >> 8;
    int r = (tid >> 6) & 3;
    int v = tid & 63;
    const float* mp = mem + (size_t)b * NN * VV + v;
    float acc = 0.f;
#pragma unroll 4
    for (int nn = half * 256; nn < half * 256 + 256; nn++)
        acc += swr[r][nn] * mp[(size_t)nn * 64];
    sred[tid] = acc;
    __syncthreads();
    if (tid < 256) srv[tid] = sred[tid] + sred[tid + 256];
    __syncthreads();

    for (int k = tid; k < 896; k += 512) {
        float val;
        if (k < 128) val = x[b * 128 + k];
        else if (k < 384) val = srv[k - 128];
        else val = h[b * 512 + (k - 384)];
        g_inT[k * 64 + b] = val;
    }
}

// ============================================================
// 4) gates GEMM: (64 x 2048), K=896 split into 4 partials
// ============================================================
__global__ void k_gates(const float* __restrict__ Wih, const float* __restrict__ Whh) {
    __shared__ __align__(16) float Wt[16][68];
    __shared__ __align__(16) float It[16][68];
    int tid = threadIdx.x;
    int ks = blockIdx.y;
    int koff = (ks < 2) ? ks * 192 : 384 + (ks - 2) * 256;
    int klen = (ks < 2) ? 192 : 256;
    int j0 = blockIdx.x * 64;
    int tx = tid & 15, ty = tid >> 4;
    float acc[4][4];
#pragma unroll
    for (int i = 0; i < 4; i++)
#pragma unroll
        for (int j = 0; j < 4; j++) acc[i][j] = 0.f;
    int jj = tid >> 2, kq = tid & 3;
    for (int kst = 0; kst < klen; kst += 16) {
        int vk = koff + kst + kq * 4;
        const float* wp = (vk < 384) ? (Wih + (j0 + jj) * 384 + vk)
                                     : (Whh + (j0 + jj) * 512 + (vk - 384));
        float4 wv = *(const float4*)wp;
        Wt[kq * 4 + 0][jj] = wv.x;
        Wt[kq * 4 + 1][jj] = wv.y;
        Wt[kq * 4 + 2][jj] = wv.z;
        Wt[kq * 4 + 3][jj] = wv.w;
        *(float4*)&It[ty][tx * 4] = *(const float4*)&g_inT[(koff + kst + ty) * 64 + tx * 4];
        __syncthreads();
#pragma unroll
        for (int kk = 0; kk < 16; kk++) {
            float4 av = *(float4*)&It[kk][tx * 4];
            float4 wv2 = *(float4*)&Wt[kk][ty * 4];
            acc[0][0] += wv2.x * av.x; acc[0][1] += wv2.x * av.y; acc[0][2] += wv2.x * av.z; acc[0][3] += wv2.x * av.w;
            acc[1][0] += wv2.y * av.x; acc[1][1] += wv2.y * av.y; acc[1][2] += wv2.y * av.z; acc[1][3] += wv2.y * av.w;
            acc[2][0] += wv2.z * av.x; acc[2][1] += wv2.z * av.y; acc[2][2] += wv2.z * av.z; acc[2][3] += wv2.z * av.w;
            acc[3][0] += wv2.w * av.x; acc[3][1] += wv2.w * av.y; acc[3][2] += wv2.w * av.z; acc[3][3] += wv2.w * av.w;
        }
        __syncthreads();
    }
#pragma unroll
    for (int jq = 0; jq < 4; jq++)
#pragma unroll
        for (int bq = 0; bq < 4; bq++)
            g_gpart[(((size_t)ks * 64 + (tx * 4 + bq)) * 2048) + j0 + ty * 4 + jq] = acc[jq][bq];
}

// ============================================================
// 5) LSTM activations
// ============================================================
__global__ void k_lstm(const float* __restrict__ c, const float* __restrict__ bih,
                       const float* __restrict__ bhh, float* __restrict__ out) {
    int gid = blockIdx.x * 256 + threadIdx.x;  // < 32768
    int b = gid >> 9, hh = gid & 511;
    float gi = bih[hh] + bhh[hh];
    float gf = bih[512 + hh] + bhh[512 + hh];
    float gg = bih[1024 + hh] + bhh[1024 + hh];
    float go = bih[1536 + hh] + bhh[1536 + hh];
#pragma unroll
    for (int ks = 0; ks < 4; ks++) {
        const float* gp = g_gpart + ((size_t)(ks * 64 + b) * 2048);
        gi += gp[hh];
        gf += gp[512 + hh];
        gg += gp[1024 + hh];
        go += gp[1536 + hh];
    }
    float cn = sigf(gf) * c[gid] + sigf(gi) * tanhf(gg);
    float hn = sigf(go) * tanhf(cn);
    out[OUT_C + gid] = cn;
    out[OUT_H + gid] = hn;
}

// ============================================================
// 6) output projections: wo(195), logits(18), value(1)
// ============================================================
__global__ void k_outproj(const float* __restrict__ Ww, const float* __restrict__ bw_,
                          const float* __restrict__ Wp, const float* __restrict__ bp,
                          const float* __restrict__ Wv, const float* __restrict__ bv,
                          const float* __restrict__ out_h, float* __restrict__ out) {
    int lane = threadIdx.x & 31;
    int row = blockIdx.x * 8 + (threadIdx.x >> 5);
    if (row >= 214) return;
    int b = blockIdx.y * 32 + lane;
    const float* wrow;
    float bias;
    if (row < 195)      { wrow = Ww + row * 512;         bias = bw_[row]; }
    else if (row < 213) { wrow = Wp + (row - 195) * 512; bias = bp[row - 195]; }
    else                { wrow = Wv;                     bias = bv[0]; }
    const float4* w4 = (const float4*)wrow;
    const float4* h4 = (const float4*)(out_h + b * 512);
    float acc = bias;
#pragma unroll 8
    for (int k = 0; k < 128; k++) {
        float4 w = w4[k], v = h4[k];
        acc += w.x * v.x + w.y * v.y + w.z * v.z + w.w * v.w;
    }
    if (row < 195)      g_wo[b * 256 + row] = acc;
    else if (row < 213) out[OUT_LOGITS + b * 18 + (row - 195)] = acc;
    else                out[OUT_VALUE + b] = acc;
}

// ============================================================
// 7) fused per-b write path
// ============================================================
__global__ void k_wall(const float* __restrict__ mem, const float* __restrict__ usage,
                       const float* __restrict__ wwin, const float* __restrict__ prec,
                       float* __restrict__ out) {
    int b = blockIdx.x, tid = threadIdx.x;  // 512 threads
    __shared__ __align__(16) float skey[64];
    __shared__ float part[2];
    __shared__ float salloc[512];
    __shared__ float sv[512];
    __shared__ float sp[512];
    __shared__ int si[512];
    __shared__ float red[16];
    __shared__ float s_beta, s_knorm, s_ga, s_gw, s_m, s_sum, s_ws;
    int lane = tid & 31, wid = tid >> 5;

    if (tid < 64) {
        float kv = g_wo[b * 256 + tid];
        skey[tid] = kv;
        g_erase[b * 64 + tid] = sigf(g_wo[b * 256 + 64 + tid]);
        g_add[b * 64 + tid] = tanhf(g_wo[b * 256 + 128 + tid]);
        float s = kv * kv;
#pragma unroll
        for (int o = 16; o > 0; o >>= 1) s += __shfl_down_sync(0xffffffffu, s, o);
        if (lane == 0) part[tid >> 5] = s;
    }
    __syncthreads();
    if (tid == 0) {
        s_knorm = fmaxf(sqrtf(part[0] + part[1]), EPSF);
        s_beta = softplusf(g_wo[b * 256 + 192]);
        s_ga = sigf(g_wo[b * 256 + 193]);
        s_gw = sigf(g_wo[b * 256 + 194]);
    }
    __syncthreads();

    const float4* mrow = (const float4*)(mem + ((size_t)b * NN + tid) * VV);
    float acc = 0.f;
#pragma unroll
    for (int i = 0; i < 16; i++) {
        float4 m4 = mrow[i];
        acc += m4.x * skey[4 * i] + m4.y * skey[4 * i + 1] + m4.z * skey[4 * i + 2] + m4.w * skey[4 * i + 3];
    }
    float sim = s_beta * acc / (g_memnorm[b * NN + tid] * s_knorm);

    float v = sim;
#pragma unroll
    for (int o = 16; o > 0; o >>= 1) v = fmaxf(v, __shfl_down_sync(0xffffffffu, v, o));
    if (lane == 0) red[wid] = v;
    __syncthreads();
    if (tid == 0) {
        float m = red[0];
#pragma unroll
        for (int i = 1; i < 16; i++) m = fmaxf(m, red[i]);
        s_m = m;
    }
    __syncthreads();
    float e = expf(sim - s_m);
    v = e;
#pragma unroll
    for (int o = 16; o > 0; o >>= 1) v += __shfl_down_sync(0xffffffffu, v, o);
    if (lane == 0) red[wid] = v;
    __syncthreads();
    if (tid == 0) {
        float t = 0.f;
#pragma unroll
        for (int i = 0; i < 16; i++) t += red[i];
        s_sum = t;
    }
    __syncthreads();
    float cww = e / s_sum;

    sv[tid] = usage[b * 512 + tid];
    si[tid] = tid;
    __syncthreads();
    for (int k = 2; k <= 512; k <<= 1)
        for (int j = k >> 1; j > 0; j >>= 1) {
            int ixj = tid ^ j;
            if (ixj > tid) {
                float a = sv[tid], c = sv[ixj];
                bool up = ((tid & k) == 0);
                if ((a > c) == up) {
                    sv[tid] = c; sv[ixj] = a;
                    int t = si[tid]; si[tid] = si[ixj]; si[ixj] = t;
                }
            }
            __syncthreads();
        }
    sp[tid] = sv[tid];
    __syncthreads();
    for (int off = 1; off < 512; off <<= 1) {
        float t = (tid >= off) ? sp[tid - off] : 1.f;
        __syncthreads();
        sp[tid] *= t;
        __syncthreads();
    }
    float excl = (tid == 0) ? 1.f : sp[tid - 1];
    salloc[si[tid]] = (1.f - sv[tid]) * excl;
    __syncthreads();

    float ww = s_gw * (s_ga * salloc[tid] + (1.f - s_ga) * cww);
    out[OUT_WW + b * 512 + tid] = ww;
    v = ww;
#pragma unroll
    for (int o = 16; o > 0; o >>= 1) v += __shfl_down_sync(0xffffffffu, v, o);
    if (lane == 0) red[wid] = v;
    __syncthreads();
    if (tid == 0) {
        float t = 0.f;
#pragma unroll
        for (int i = 0; i < 16; i++) t += red[i];
        s_ws = t;
    }
    __syncthreads();
    out[OUT_PREC + b * 512 + tid] = (1.f - s_ws) * prec[b * 512 + tid] + ww;
    float u = usage[b * 512 + tid], w0 = wwin[b * 512 + tid];
    out[OUT_USAGE + b * 512 + tid] = (u + w0 - u * w0) * g_psi[b * 512 + tid];
}

// ============================================================
// 8) fused memory + link update
// ============================================================
__global__ void k_memlink(const float* __restrict__ mem, const float* __restrict__ link,
                          const float* __restrict__ prec, float* __restrict__ out) {
    int bx = blockIdx.x;
    if (bx < 2048) {
        int gid = bx * 256 + threadIdx.x;
        int v4 = gid & 15, n = (gid >> 4) & 511, b = gid >> 13;
        float4 m = ((const float4*)mem)[gid];
        float ww = out[OUT_WW + b * 512 + n];
        float4 er = ((const float4*)g_erase)[b * 16 + v4];
        float4 ad = ((const float4*)g_add)[b * 16 + v4];
        float4 r;
        r.x = m.x * (1.f - ww * er.x) + ww * ad.x;
        r.y = m.y * (1.f - ww * er.y) + ww * ad.y;
        r.z = m.z * (1.f - ww * er.z) + ww * ad.z;
        r.w = m.w * (1.f - ww * er.w) + ww * ad.w;
        ((float4*)(out + OUT_MEM))[gid] = r;
    } else {
        int gid = (bx - 2048) * 256 + threadIdx.x;
        int mq = gid & 127, n = (gid >> 7) & 511, b = gid >> 16;
        float4 l = ((const float4*)link)[gid];
        float wn = out[OUT_WW + b * 512 + n];
        float4 wm = ((const float4*)(out + OUT_WW + b * 512))[mq];
        float4 p = ((const float4*)(prec + b * 512))[mq];
        float om = 1.f - wn;
        float4 r;
        r.x = om * (1.f - wm.x) * l.x + wn * p.x;
        r.y = om * (1.f - wm.y) * l.y + wn * p.y;
        r.z = om * (1.f - wm.z) * l.z + wn * p.z;
        r.w = om * (1.f - wm.w) * l.w + wn * p.w;
        int m0 = mq * 4;
        if (m0 == n)     r.x = 0.f;
        if (m0 + 1 == n) r.y = 0.f;
        if (m0 + 2 == n) r.z = 0.f;
        if (m0 + 3 == n) r.w = 0.f;
        ((float4*)(out + OUT_LINK))[gid] = r;
    }
}

extern "C" void kernel_launch(void* const* d_in, const int* in_sizes, int n_in,
                              void* d_out, int out_size) {
    const float* x             = (const float*)d_in[0];
    const float* h             = (const float*)d_in[1];
    const float* c             = (const float*)d_in[2];
    const float* memory        = (const float*)d_in[3];
    const float* read_weights  = (const float*)d_in[4];
    const float* write_weights = (const float*)d_in[5];
    const float* usage         = (const float*)d_in[6];
    const float* link          = (const float*)d_in[7];
    const float* prec          = (const float*)d_in[8];
    const float* W_ih          = (const float*)d_in[9];
    const float* W_hh          = (const float*)d_in[10];
    const float* b_ih          = (const float*)d_in[11];
    const float* b_hh          = (const float*)d_in[12];
    const float* W_read        = (const float*)d_in[13];
    const float* b_read        = (const float*)d_in[14];
    const float* W_write       = (const float*)d_in[15];
    const float* b_write       = (const float*)d_in[16];
    const float* W_pol         = (const float*)d_in[17];
    const float* b_pol         = (const float*)d_in[18];
    const float* W_val         = (const float*)d_in[19];
    const float* b_val         = (const float*)d_in[20];
    float* out = (float*)d_out;

    k_pre<<<4164, 256>>>(W_read, b_read, h, memory);
    k_big<<<2816, 512>>>(memory, link, read_weights);
    k_mix<<<64, 512>>>(memory, x, h, out);
    k_gates<<<dim3(32, 4), 256>>>(W_ih, W_hh);
    k_lstm<<<128, 256>>>(c, b_ih, b_hh, out);
    k_outproj<<<dim3(27, 2), 256>>>(W_write, b_write, W_pol, b_pol, W_val, b_val, out + OUT_H, out);
    k_wall<<<64, 512>>>(memory, usage, write_weights, prec, out);
    k_memlink<<<18432, 256>>>(memory, link, prec, out);
}

// round 5
// speedup vs baseline: 1.6620x; 1.0839x over previous
#include <cuda_runtime.h>
#include <math.h>

#define BB 64
#define NN 512
#define VV 64
#define HH 512
#define RR 4
#define KK 32
#define EPSF 1e-8f

// output offsets (floats), tuple order:
// logits, value, h_new, c_new, mem_new, w_r, write_w, usage_new, link_new, prec_new
#define OUT_LOGITS 0
#define OUT_VALUE  1152
#define OUT_H      1216
#define OUT_C      33984
#define OUT_MEM    66752
#define OUT_WR     2163904
#define OUT_WW     2294976
#define OUT_USAGE  2327744
#define OUT_LINK   2360512
#define OUT_PREC   19137728

// workspace
__device__ __align__(16) float g_ro[BB * 272];
__device__ __align__(16) float g_rpi[BB * RR * 3];
__device__ __align__(16) float g_memnorm[BB * NN];
__device__ __align__(16) float g_cw[BB * RR * NN];
__device__ __align__(16) float g_fw[BB * RR * NN];
__device__ __align__(16) float g_bwp[8 * BB * RR * NN];
__device__ __align__(16) float g_psi[BB * NN];
__device__ __align__(16) float g_inT[896 * BB];
__device__ __align__(16) float g_gpart[8 * BB * 2048];
__device__ __align__(16) float g_wo[BB * 256];
__device__ __align__(16) float g_erase[BB * VV];
__device__ __align__(16) float g_add[BB * VV];

__device__ __forceinline__ float sigf(float x) { return 1.f / (1.f + expf(-x)); }
__device__ __forceinline__ float softplusf(float x) { return x > 20.f ? x : log1pf(expf(x)); }
__device__ __forceinline__ unsigned f2o(float f) {
    unsigned u = __float_as_uint(f);
    return (u & 0x80000000u) ? ~u : (u | 0x80000000u);
}

// ============================================================
// 1) fused: readproj (blocks 0..67) + memnorm (blocks 68..4163)
// ============================================================
__global__ void k_pre(const float* __restrict__ Wr, const float* __restrict__ br,
                      const float* __restrict__ h, const float* __restrict__ mem) {
    int lane = threadIdx.x & 31;
    int warp = threadIdx.x >> 5;
    if (blockIdx.x < 68) {
        int rp = blockIdx.x;
        int row = (rp % 34) * 8 + warp;          // 0..271
        int b   = (rp / 34) * 32 + lane;         // 0..63
        const float4* w4 = (const float4*)(Wr + row * HH);
        const float4* h4 = (const float4*)(h + b * HH);
        float acc = 0.f;
#pragma unroll 8
        for (int k = 0; k < HH / 4; k++) {
            float4 w = w4[k], v = h4[k];
            acc += w.x * v.x + w.y * v.y + w.z * v.z + w.w * v.w;
        }
        g_ro[b * 272 + row] = acc + br[row];
    } else {
        int gid = (blockIdx.x - 68) * 8 + warp;  // 32768 rows
        const float2* p = (const float2*)(mem + (size_t)gid * VV);
        float2 v = p[lane];
        float s = v.x * v.x + v.y * v.y;
#pragma unroll
        for (int o = 16; o > 0; o >>= 1) s += __shfl_down_sync(0xffffffffu, s, o);
        if (lane == 0) g_memnorm[gid] = fmaxf(sqrtf(s), EPSF);
    }
}

// ============================================================
// 2) mega-kernel: fw (2048) + bw partials (512) + content (256)
// ============================================================
__global__ void __launch_bounds__(512) k_big(const float* __restrict__ mem,
                                             const float* __restrict__ link,
                                             const float* __restrict__ rw) {
    __shared__ __align__(16) float buf[2080];
    int tid = threadIdx.x;
    int blk = blockIdx.x;

    if (blk < 2048) {
        // ---------------- fw: 16 rows per block ----------------
        int b = blk >> 5, chunk = blk & 31;
        if (tid < 512)
            ((float4*)buf)[tid] = ((const float4*)(rw + b * 2048))[tid];
        __syncthreads();
        int lane = tid & 31;
        int n = chunk * 16 + (tid >> 5);
        const float4* lrow = (const float4*)(link + ((size_t)b * NN + n) * NN);
        float a0 = 0.f, a1 = 0.f, a2 = 0.f, a3 = 0.f;
#pragma unroll
        for (int i = 0; i < 4; i++) {
            int mq = lane + 32 * i;
            float4 l = lrow[mq];
            float4 w0 = *(const float4*)&buf[mq * 4];
            float4 w1 = *(const float4*)&buf[512 + mq * 4];
            float4 w2 = *(const float4*)&buf[1024 + mq * 4];
            float4 w3 = *(const float4*)&buf[1536 + mq * 4];
            a0 += l.x * w0.x + l.y * w0.y + l.z * w0.z + l.w * w0.w;
            a1 += l.x * w1.x + l.y * w1.y + l.z * w1.z + l.w * w1.w;
            a2 += l.x * w2.x + l.y * w2.y + l.z * w2.z + l.w * w2.w;
            a3 += l.x * w3.x + l.y * w3.y + l.z * w3.z + l.w * w3.w;
        }
#pragma unroll
        for (int o = 16; o > 0; o >>= 1) {
            a0 += __shfl_down_sync(0xffffffffu, a0, o);
            a1 += __shfl_down_sync(0xffffffffu, a1, o);
            a2 += __shfl_down_sync(0xffffffffu, a2, o);
            a3 += __shfl_down_sync(0xffffffffu, a3, o);
        }
        if (lane == 0) {
            g_fw[(b * 4 + 0) * 512 + n] = a0;
            g_fw[(b * 4 + 1) * 512 + n] = a1;
            g_fw[(b * 4 + 2) * 512 + n] = a2;
            g_fw[(b * 4 + 3) * 512 + n] = a3;
        }
    } else if (blk < 2560) {
        // ---------------- bw partial: 64 rows (chunk mc), all 512 cols ----------------
        int idx = blk - 2048;
        int b = idx >> 3, mc = idx & 7;
        if (tid < 256)
            buf[tid] = rw[b * 2048 + (tid >> 6) * 512 + mc * 64 + (tid & 63)];
        __syncthreads();
        int n = tid;
        const float* lp = link + ((size_t)b * NN + mc * 64) * NN + n;
        float a0 = 0.f, a1 = 0.f, a2 = 0.f, a3 = 0.f;
#pragma unroll 8
        for (int m = 0; m < 64; m++) {
            float l = lp[(size_t)m * 512];
            a0 += l * buf[m];
            a1 += l * buf[64 + m];
            a2 += l * buf[128 + m];
            a3 += l * buf[192 + m];
        }
        size_t base = (((size_t)mc * 64 + b) * 4) * 512 + n;
        g_bwp[base]        = a0;
        g_bwp[base + 512]  = a1;
        g_bwp[base + 1024] = a2;
        g_bwp[base + 1536] = a3;
    } else {
        // ---------------- content: per (b,r), radix-select top-K ----------------
        int idx = blk - 2560;
        int b = idx >> 2, r = idx & 3;
        float* key = buf;             // 64
        float* red = buf + 64;        // 16
        float* sc  = buf + 80;        // beta, kn, tot
        int lane = tid & 31, wid = tid >> 5;

        if (tid < 64) key[tid] = g_ro[b * 272 + r * 68 + tid];
        __syncthreads();
        if (tid == 0) {
            sc[0] = softplusf(g_ro[b * 272 + r * 68 + 64]);
            float p0 = g_ro[b * 272 + r * 68 + 65];
            float p1 = g_ro[b * 272 + r * 68 + 66];
            float p2 = g_ro[b * 272 + r * 68 + 67];
            float mx = fmaxf(p0, fmaxf(p1, p2));
            float e0 = expf(p0 - mx), e1 = expf(p1 - mx), e2 = expf(p2 - mx);
            float inv = 1.f / (e0 + e1 + e2);
            g_rpi[(b * 4 + r) * 3 + 0] = e0 * inv;
            g_rpi[(b * 4 + r) * 3 + 1] = e1 * inv;
            g_rpi[(b * 4 + r) * 3 + 2] = e2 * inv;
        }
        if (tid < 32) {
            float v = key[tid] * key[tid] + key[tid + 32] * key[tid + 32];
#pragma unroll
            for (int o = 16; o > 0; o >>= 1) v += __shfl_down_sync(0xffffffffu, v, o);
            if (tid == 0) sc[1] = fmaxf(sqrtf(v), EPSF);
        }
        __syncthreads();

        const float4* mrow = (const float4*)(mem + ((size_t)b * NN + tid) * VV);
        float acc = 0.f;
#pragma unroll
        for (int i = 0; i < 16; i++) {
            float4 m4 = mrow[i];
            acc += m4.x * key[4 * i] + m4.y * key[4 * i + 1] + m4.z * key[4 * i + 2] + m4.w * key[4 * i + 3];
        }
        float score = sc[0] * acc / (g_memnorm[b * NN + tid] * sc[1]);
        unsigned u = f2o(score);

        // radix-select: largest T with count(u >= T) >= K  ==  kth-largest value
        unsigned prefix = 0u;
#pragma unroll
        for (int bit = 31; bit >= 0; --bit) {
            unsigned cand = prefix | (1u << bit);
            int cnt = __syncthreads_count(u >= cand);
            if (cnt >= KK) prefix = cand;
        }

        // scores bounded by beta (|cos|<=1): exp without max-shift is safe
        float e = (u >= prefix) ? expf(score) : 0.f;
        float v = e;
#pragma unroll
        for (int o = 16; o > 0; o >>= 1) v += __shfl_down_sync(0xffffffffu, v, o);
        if (lane == 0) red[wid] = v;
        __syncthreads();
        if (tid == 0) {
            float t = 0.f;
#pragma unroll
            for (int i = 0; i < 16; i++) t += red[i];
            sc[2] = t;
        }
        __syncthreads();
        g_cw[(b * 4 + r) * 512 + tid] = e / sc[2];
    }
}

// ============================================================
// 3) fused per-b: w_r mix + psi + rvec + pack inT
// ============================================================
__global__ void k_mix(const float* __restrict__ mem, const float* __restrict__ x,
                      const float* __restrict__ h, float* __restrict__ out) {
    int b = blockIdx.x, tid = threadIdx.x;  // 512 threads
    __shared__ float swr[4][512];
    __shared__ float sred[512];
    __shared__ float srv[256];
    int n = tid;
    float psi = 1.f;
#pragma unroll
    for (int r = 0; r < 4; r++) {
        int o = (b * 4 + r) * 512 + n;
        float bwv = 0.f;
#pragma unroll
        for (int mc = 0; mc < 8; mc++)
            bwv += g_bwp[((size_t)(mc * 64 + b) * 4 + r) * 512 + n];
        float p0 = g_rpi[(b * 4 + r) * 3 + 0];
        float p1 = g_rpi[(b * 4 + r) * 3 + 1];
        float p2 = g_rpi[(b * 4 + r) * 3 + 2];
        float wr = p0 * bwv + p1 * g_cw[o] + p2 * g_fw[o];
        swr[r][n] = wr;
        out[OUT_WR + o] = wr;
        psi *= (1.f - wr);
    }
    g_psi[b * 512 + n] = psi;
    __syncthreads();

    int half = tid >> 8;
    int r = (tid >> 6) & 3;
    int v = tid & 63;
    const float* mp = mem + (size_t)b * NN * VV + v;
    float acc = 0.f;
#pragma unroll 4
    for (int nn = half * 256; nn < half * 256 + 256; nn++)
        acc += swr[r][nn] * mp[(size_t)nn * 64];
    sred[tid] = acc;
    __syncthreads();
    if (tid < 256) srv[tid] = sred[tid] + sred[tid + 256];
    __syncthreads();

    for (int k = tid; k < 896; k += 512) {
        float val;
        if (k < 128) val = x[b * 128 + k];
        else if (k < 384) val = srv[k - 128];
        else val = h[b * 512 + (k - 384)];
        g_inT[k * 64 + b] = val;
    }
}

// ============================================================
// 4) gates GEMM: (64 x 2048), K=896 split into 8 partials of 112
// ============================================================
__global__ void __launch_bounds__(256) k_gates(const float* __restrict__ Wih,
                                               const float* __restrict__ Whh) {
    __shared__ __align__(16) float Wt[16][68];
    __shared__ __align__(16) float It[16][68];
    int tid = threadIdx.x;
    int ks = blockIdx.y;           // 0..7
    int koff = ks * 112;
    int j0 = blockIdx.x * 64;
    int tx = tid & 15, ty = tid >> 4;
    float acc[4][4];
#pragma unroll
    for (int i = 0; i < 4; i++)
#pragma unroll
        for (int j = 0; j < 4; j++) acc[i][j] = 0.f;
    int jj = tid >> 2, kq = tid & 3;
    for (int kst = 0; kst < 112; kst += 16) {
        int vk = koff + kst + kq * 4;
        const float* wp = (vk < 384) ? (Wih + (j0 + jj) * 384 + vk)
                                     : (Whh + (j0 + jj) * 512 + (vk - 384));
        float4 wv = *(const float4*)wp;
        Wt[kq * 4 + 0][jj] = wv.x;
        Wt[kq * 4 + 1][jj] = wv.y;
        Wt[kq * 4 + 2][jj] = wv.z;
        Wt[kq * 4 + 3][jj] = wv.w;
        *(float4*)&It[ty][tx * 4] = *(const float4*)&g_inT[(koff + kst + ty) * 64 + tx * 4];
        __syncthreads();
#pragma unroll
        for (int kk = 0; kk < 16; kk++) {
            float4 av = *(float4*)&It[kk][tx * 4];
            float4 wv2 = *(float4*)&Wt[kk][ty * 4];
            acc[0][0] += wv2.x * av.x; acc[0][1] += wv2.x * av.y; acc[0][2] += wv2.x * av.z; acc[0][3] += wv2.x * av.w;
            acc[1][0] += wv2.y * av.x; acc[1][1] += wv2.y * av.y; acc[1][2] += wv2.y * av.z; acc[1][3] += wv2.y * av.w;
            acc[2][0] += wv2.z * av.x; acc[2][1] += wv2.z * av.y; acc[2][2] += wv2.z * av.z; acc[2][3] += wv2.z * av.w;
            acc[3][0] += wv2.w * av.x; acc[3][1] += wv2.w * av.y; acc[3][2] += wv2.w * av.z; acc[3][3] += wv2.w * av.w;
        }
        __syncthreads();
    }
#pragma unroll
    for (int jq = 0; jq < 4; jq++)
#pragma unroll
        for (int bq = 0; bq < 4; bq++)
            g_gpart[(((size_t)ks * 64 + (tx * 4 + bq)) * 2048) + j0 + ty * 4 + jq] = acc[jq][bq];
}

// ============================================================
// 5) fused LSTM + output projections (per-b block)
// ============================================================
__global__ void __launch_bounds__(512) k_hout(
    const float* __restrict__ c, const float* __restrict__ bih, const float* __restrict__ bhh,
    const float* __restrict__ Ww, const float* __restrict__ bw_,
    const float* __restrict__ Wp, const float* __restrict__ bp,
    const float* __restrict__ Wv, const float* __restrict__ bv,
    float* __restrict__ out) {
    int b = blockIdx.x, tid = threadIdx.x;
    __shared__ __align__(16) float sh[512];

    float gi = bih[tid] + bhh[tid];
    float gf = bih[512 + tid] + bhh[512 + tid];
    float gg = bih[1024 + tid] + bhh[1024 + tid];
    float go = bih[1536 + tid] + bhh[1536 + tid];
#pragma unroll
    for (int ks = 0; ks < 8; ks++) {
        const float* gp = g_gpart + ((size_t)(ks * 64 + b) * 2048);
        gi += gp[tid];
        gf += gp[512 + tid];
        gg += gp[1024 + tid];
        go += gp[1536 + tid];
    }
    float cn = sigf(gf) * c[b * 512 + tid] + sigf(gi) * tanhf(gg);
    float hn = sigf(go) * tanhf(cn);
    out[OUT_C + b * 512 + tid] = cn;
    out[OUT_H + b * 512 + tid] = hn;
    sh[tid] = hn;
    __syncthreads();

    int lane = tid & 31, w = tid >> 5;
    for (int row = w; row < 214; row += 16) {
        const float* wrow;
        float bias;
        if (row < 195)      { wrow = Ww + row * 512;         bias = bw_[row]; }
        else if (row < 213) { wrow = Wp + (row - 195) * 512; bias = bp[row - 195]; }
        else                { wrow = Wv;                     bias = bv[0]; }
        const float4* w4 = (const float4*)wrow;
        float acc = 0.f;
#pragma unroll
        for (int i = 0; i < 4; i++) {
            float4 wv = w4[lane + 32 * i];
            float4 hv = *(const float4*)&sh[(lane + 32 * i) * 4];
            acc += wv.x * hv.x + wv.y * hv.y + wv.z * hv.z + wv.w * hv.w;
        }
#pragma unroll
        for (int o = 16; o > 0; o >>= 1) acc += __shfl_down_sync(0xffffffffu, acc, o);
        if (lane == 0) {
            acc += bias;
            if (row < 195)      g_wo[b * 256 + row] = acc;
            else if (row < 213) out[OUT_LOGITS + b * 18 + (row - 195)] = acc;
            else                out[OUT_VALUE + b] = acc;
        }
    }
}

// ============================================================
// 6) fused per-b write path
// ============================================================
__global__ void k_wall(const float* __restrict__ mem, const float* __restrict__ usage,
                       const float* __restrict__ wwin, const float* __restrict__ prec,
                       float* __restrict__ out) {
    int b = blockIdx.x, tid = threadIdx.x;  // 512 threads
    __shared__ __align__(16) float skey[64];
    __shared__ float part[2];
    __shared__ float salloc[512];
    __shared__ float sv[512];
    __shared__ float sp[512];
    __shared__ int si[512];
    __shared__ float red[16];
    __shared__ float s_beta, s_knorm, s_ga, s_gw, s_m, s_sum, s_ws;
    int lane = tid & 31, wid = tid >> 5;

    if (tid < 64) {
        float kv = g_wo[b * 256 + tid];
        skey[tid] = kv;
        g_erase[b * 64 + tid] = sigf(g_wo[b * 256 + 64 + tid]);
        g_add[b * 64 + tid] = tanhf(g_wo[b * 256 + 128 + tid]);
        float s = kv * kv;
#pragma unroll
        for (int o = 16; o > 0; o >>= 1) s += __shfl_down_sync(0xffffffffu, s, o);
        if (lane == 0) part[tid >> 5] = s;
    }
    __syncthreads();
    if (tid == 0) {
        s_knorm = fmaxf(sqrtf(part[0] + part[1]), EPSF);
        s_beta = softplusf(g_wo[b * 256 + 192]);
        s_ga = sigf(g_wo[b * 256 + 193]);
        s_gw = sigf(g_wo[b * 256 + 194]);
    }
    __syncthreads();

    const float4* mrow = (const float4*)(mem + ((size_t)b * NN + tid) * VV);
    float acc = 0.f;
#pragma unroll
    for (int i = 0; i < 16; i++) {
        float4 m4 = mrow[i];
        acc += m4.x * skey[4 * i] + m4.y * skey[4 * i + 1] + m4.z * skey[4 * i + 2] + m4.w * skey[4 * i + 3];
    }
    float sim = s_beta * acc / (g_memnorm[b * NN + tid] * s_knorm);

    float v = sim;
#pragma unroll
    for (int o = 16; o > 0; o >>= 1) v = fmaxf(v, __shfl_down_sync(0xffffffffu, v, o));
    if (lane == 0) red[wid] = v;
    __syncthreads();
    if (tid == 0) {
        float m = red[0];
#pragma unroll
        for (int i = 1; i < 16; i++) m = fmaxf(m, red[i]);
        s_m = m;
    }
    __syncthreads();
    float e = expf(sim - s_m);
    v = e;
#pragma unroll
    for (int o = 16; o > 0; o >>= 1) v += __shfl_down_sync(0xffffffffu, v, o);
    if (lane == 0) red[wid] = v;
    __syncthreads();
    if (tid == 0) {
        float t = 0.f;
#pragma unroll
        for (int i = 0; i < 16; i++) t += red[i];
        s_sum = t;
    }
    __syncthreads();
    float cww = e / s_sum;

    sv[tid] = usage[b * 512 + tid];
    si[tid] = tid;
    __syncthreads();
    for (int k = 2; k <= 512; k <<= 1)
        for (int j = k >> 1; j > 0; j >>= 1) {
            int ixj = tid ^ j;
            if (ixj > tid) {
                float a = sv[tid], c = sv[ixj];
                bool up = ((tid & k) == 0);
                if ((a > c) == up) {
                    sv[tid] = c; sv[ixj] = a;
                    int t = si[tid]; si[tid] = si[ixj]; si[ixj] = t;
                }
            }
            __syncthreads();
        }
    sp[tid] = sv[tid];
    __syncthreads();
    for (int off = 1; off < 512; off <<= 1) {
        float t = (tid >= off) ? sp[tid - off] : 1.f;
        __syncthreads();
        sp[tid] *= t;
        __syncthreads();
    }
    float excl = (tid == 0) ? 1.f : sp[tid - 1];
    salloc[si[tid]] = (1.f - sv[tid]) * excl;
    __syncthreads();

    float ww = s_gw * (s_ga * salloc[tid] + (1.f - s_ga) * cww);
    out[OUT_WW + b * 512 + tid] = ww;
    v = ww;
#pragma unroll
    for (int o = 16; o > 0; o >>= 1) v += __shfl_down_sync(0xffffffffu, v, o);
    if (lane == 0) red[wid] = v;
    __syncthreads();
    if (tid == 0) {
        float t = 0.f;
#pragma unroll
        for (int i = 0; i < 16; i++) t += red[i];
        s_ws = t;
    }
    __syncthreads();
    out[OUT_PREC + b * 512 + tid] = (1.f - s_ws) * prec[b * 512 + tid] + ww;
    float u = usage[b * 512 + tid], w0 = wwin[b * 512 + tid];
    out[OUT_USAGE + b * 512 + tid] = (u + w0 - u * w0) * g_psi[b * 512 + tid];
}

// ============================================================
// 7) fused memory + link update
// ============================================================
__global__ void k_memlink(const float* __restrict__ mem, const float* __restrict__ link,
                          const float* __restrict__ prec, float* __restrict__ out) {
    int bx = blockIdx.x;
    if (bx < 2048) {
        int gid = bx * 256 + threadIdx.x;
        int v4 = gid & 15, n = (gid >> 4) & 511, b = gid >> 13;
        float4 m = ((const float4*)mem)[gid];
        float ww = out[OUT_WW + b * 512 + n];
        float4 er = ((const float4*)g_erase)[b * 16 + v4];
        float4 ad = ((const float4*)g_add)[b * 16 + v4];
        float4 r;
        r.x = m.x * (1.f - ww * er.x) + ww * ad.x;
        r.y = m.y * (1.f - ww * er.y) + ww * ad.y;
        r.z = m.z * (1.f - ww * er.z) + ww * ad.z;
        r.w = m.w * (1.f - ww * er.w) + ww * ad.w;
        ((float4*)(out + OUT_MEM))[gid] = r;
    } else {
        int gid = (bx - 2048) * 256 + threadIdx.x;
        int mq = gid & 127, n = (gid >> 7) & 511, b = gid >> 16;
        float4 l = ((const float4*)link)[gid];
        float wn = out[OUT_WW + b * 512 + n];
        float4 wm = ((const float4*)(out + OUT_WW + b * 512))[mq];
        float4 p = ((const float4*)(prec + b * 512))[mq];
        float om = 1.f - wn;
        float4 r;
        r.x = om * (1.f - wm.x) * l.x + wn * p.x;
        r.y = om * (1.f - wm.y) * l.y + wn * p.y;
        r.z = om * (1.f - wm.z) * l.z + wn * p.z;
        r.w = om * (1.f - wm.w) * l.w + wn * p.w;
        int m0 = mq * 4;
        if (m0 == n)     r.x = 0.f;
        if (m0 + 1 == n) r.y = 0.f;
        if (m0 + 2 == n) r.z = 0.f;
        if (m0 + 3 == n) r.w = 0.f;
        ((float4*)(out + OUT_LINK))[gid] = r;
    }
}

extern "C" void kernel_launch(void* const* d_in, const int* in_sizes, int n_in,
                              void* d_out, int out_size) {
    const float* x             = (const float*)d_in[0];
    const float* h             = (const float*)d_in[1];
    const float* c             = (const float*)d_in[2];
    const float* memory        = (const float*)d_in[3];
    const float* read_weights  = (const float*)d_in[4];
    const float* write_weights = (const float*)d_in[5];
    const float* usage         = (const float*)d_in[6];
    const float* link          = (const float*)d_in[7];
    const float* prec          = (const float*)d_in[8];
    const float* W_ih          = (const float*)d_in[9];
    const float* W_hh          = (const float*)d_in[10];
    const float* b_ih          = (const float*)d_in[11];
    const float* b_hh          = (const float*)d_in[12];
    const float* W_read        = (const float*)d_in[13];
    const float* b_read        = (const float*)d_in[14];
    const float* W_write       = (const float*)d_in[15];
    const float* b_write       = (const float*)d_in[16];
    const float* W_pol         = (const float*)d_in[17];
    const float* b_pol         = (const float*)d_in[18];
    const float* W_val         = (const float*)d_in[19];
    const float* b_val         = (const float*)d_in[20];
    float* out = (float*)d_out;

    k_pre<<<4164, 256>>>(W_read, b_read, h, memory);
    k_big<<<2816, 512>>>(memory, link, read_weights);
    k_mix<<<64, 512>>>(memory, x, h, out);
    k_gates<<<dim3(32, 8), 256>>>(W_ih, W_hh);
    k_hout<<<64, 512>>>(c, b_ih, b_hh, W_write, b_write, W_pol, b_pol, W_val, b_val, out);
    k_wall<<<64, 512>>>(memory, usage, write_weights, prec, out);
    k_memlink<<<18432, 256>>>(memory, link, prec, out);
}

// round 7
// speedup vs baseline: 1.9511x; 1.1739x over previous
#include <cuda_runtime.h>
#include <math.h>

#define BB 64
#define NN 512
#define VV 64
#define HH 512
#define RR 4
#define KK 32
#define EPSF 1e-8f

// output offsets (floats), tuple order:
// logits, value, h_new, c_new, mem_new, w_r, write_w, usage_new, link_new, prec_new
#define OUT_LOGITS 0
#define OUT_VALUE  1152
#define OUT_H      1216
#define OUT_C      33984
#define OUT_MEM    66752
#define OUT_WR     2163904
#define OUT_WW     2294976
#define OUT_USAGE  2327744
#define OUT_LINK   2360512
#define OUT_PREC   19137728

// workspace
__device__ __align__(16) float g_rpi[BB * RR * 3];
__device__ __align__(16) float g_cw[BB * RR * NN];
__device__ __align__(16) float g_fw[BB * RR * NN];
__device__ __align__(16) float g_bwp[8 * BB * RR * NN];
__device__ __align__(16) float g_psi[BB * NN];
__device__ __align__(16) float g_inT[896 * BB];
__device__ __align__(16) float g_gpart[7 * BB * 2048];
__device__ __align__(16) float g_erase[BB * VV];
__device__ __align__(16) float g_add[BB * VV];

__device__ __forceinline__ float sigf(float x) { return 1.f / (1.f + expf(-x)); }
__device__ __forceinline__ float softplusf(float x) { return x > 20.f ? x : log1pf(expf(x)); }
__device__ __forceinline__ unsigned f2o(float f) {
    unsigned u = __float_as_uint(f);
    return (u & 0x80000000u) ? ~u : (u | 0x80000000u);
}

// ============================================================
// 1) mega-kernel: content+readproj (256) | fw (2048) | bw partials (512)
// ============================================================
__global__ void __launch_bounds__(512) k_big(const float* __restrict__ mem,
                                             const float* __restrict__ link,
                                             const float* __restrict__ rw,
                                             const float* __restrict__ h,
                                             const float* __restrict__ Wr,
                                             const float* __restrict__ br) {
    __shared__ __align__(16) float buf[2080];
    int tid = threadIdx.x;
    int blk = blockIdx.x;

    if (blk < 256) {
        // ---------------- content per (b,r): inline read-projection ----------------
        int b = blk >> 2, r = blk & 3;
        float* hsh  = buf;          // 512
        float* rosh = buf + 512;    // 68
        float* red  = buf + 580;    // 16
        float* sc   = buf + 596;    // beta, kn, tot
        int lane = tid & 31, warp = tid >> 5;

        hsh[tid] = h[b * 512 + tid];
        __syncthreads();

        // ro rows r*68 .. r*68+67 (warp per row)
        for (int row = warp; row < 68; row += 16) {
            const float4* w4 = (const float4*)(Wr + (size_t)(r * 68 + row) * HH);
            float a = 0.f;
#pragma unroll
            for (int i = 0; i < 4; i++) {
                float4 w = w4[lane + 32 * i];
                float4 hv = *(const float4*)&hsh[(lane + 32 * i) * 4];
                a += w.x * hv.x + w.y * hv.y + w.z * hv.z + w.w * hv.w;
            }
#pragma unroll
            for (int o = 16; o > 0; o >>= 1) a += __shfl_down_sync(0xffffffffu, a, o);
            if (lane == 0) rosh[row] = a + br[r * 68 + row];
        }
        __syncthreads();

        if (tid == 0) {
            sc[0] = softplusf(rosh[64]);
            float p0 = rosh[65], p1 = rosh[66], p2 = rosh[67];
            float mx = fmaxf(p0, fmaxf(p1, p2));
            float e0 = expf(p0 - mx), e1 = expf(p1 - mx), e2 = expf(p2 - mx);
            float inv = 1.f / (e0 + e1 + e2);
            g_rpi[(b * 4 + r) * 3 + 0] = e0 * inv;
            g_rpi[(b * 4 + r) * 3 + 1] = e1 * inv;
            g_rpi[(b * 4 + r) * 3 + 2] = e2 * inv;
        }
        if (tid < 32) {
            float v = rosh[tid] * rosh[tid] + rosh[tid + 32] * rosh[tid + 32];
#pragma unroll
            for (int o = 16; o > 0; o >>= 1) v += __shfl_down_sync(0xffffffffu, v, o);
            if (tid == 0) sc[1] = fmaxf(sqrtf(v), EPSF);
        }
        __syncthreads();

        const float4* mrow = (const float4*)(mem + ((size_t)b * NN + tid) * VV);
        float acc = 0.f, nrm = 0.f;
#pragma unroll
        for (int i = 0; i < 16; i++) {
            float4 m4 = mrow[i];
            acc += m4.x * rosh[4 * i] + m4.y * rosh[4 * i + 1] + m4.z * rosh[4 * i + 2] + m4.w * rosh[4 * i + 3];
            nrm += m4.x * m4.x + m4.y * m4.y + m4.z * m4.z + m4.w * m4.w;
        }
        float score = sc[0] * acc / (fmaxf(sqrtf(nrm), EPSF) * sc[1]);
        unsigned u = f2o(score);

        // radix-select kth-largest
        unsigned prefix = 0u;
#pragma unroll
        for (int bit = 31; bit >= 0; --bit) {
            unsigned cand = prefix | (1u << bit);
            int cnt = __syncthreads_count(u >= cand);
            if (cnt >= KK) prefix = cand;
        }

        float e = (u >= prefix) ? expf(score) : 0.f;
        float v = e;
#pragma unroll
        for (int o = 16; o > 0; o >>= 1) v += __shfl_down_sync(0xffffffffu, v, o);
        if (lane == 0) red[warp] = v;
        __syncthreads();
        if (tid == 0) {
            float t = 0.f;
#pragma unroll
            for (int i = 0; i < 16; i++) t += red[i];
            sc[2] = t;
        }
        __syncthreads();
        g_cw[(b * 4 + r) * 512 + tid] = e / sc[2];
    } else if (blk < 2304) {
        // ---------------- fw: 16 rows per block ----------------
        int idx = blk - 256;
        int b = idx >> 5, chunk = idx & 31;
        ((float4*)buf)[tid] = ((const float4*)(rw + b * 2048))[tid];
        __syncthreads();
        int lane = tid & 31;
        int n = chunk * 16 + (tid >> 5);
        const float4* lrow = (const float4*)(link + ((size_t)b * NN + n) * NN);
        float a0 = 0.f, a1 = 0.f, a2 = 0.f, a3 = 0.f;
#pragma unroll
        for (int i = 0; i < 4; i++) {
            int mq = lane + 32 * i;
            float4 l = lrow[mq];
            float4 w0 = *(const float4*)&buf[mq * 4];
            float4 w1 = *(const float4*)&buf[512 + mq * 4];
            float4 w2 = *(const float4*)&buf[1024 + mq * 4];
            float4 w3 = *(const float4*)&buf[1536 + mq * 4];
            a0 += l.x * w0.x + l.y * w0.y + l.z * w0.z + l.w * w0.w;
            a1 += l.x * w1.x + l.y * w1.y + l.z * w1.z + l.w * w1.w;
            a2 += l.x * w2.x + l.y * w2.y + l.z * w2.z + l.w * w2.w;
            a3 += l.x * w3.x + l.y * w3.y + l.z * w3.z + l.w * w3.w;
        }
#pragma unroll
        for (int o = 16; o > 0; o >>= 1) {
            a0 += __shfl_down_sync(0xffffffffu, a0, o);
            a1 += __shfl_down_sync(0xffffffffu, a1, o);
            a2 += __shfl_down_sync(0xffffffffu, a2, o);
            a3 += __shfl_down_sync(0xffffffffu, a3, o);
        }
        if (lane == 0) {
            g_fw[(b * 4 + 0) * 512 + n] = a0;
            g_fw[(b * 4 + 1) * 512 + n] = a1;
            g_fw[(b * 4 + 2) * 512 + n] = a2;
            g_fw[(b * 4 + 3) * 512 + n] = a3;
        }
    } else {
        // ---------------- bw partial: 64 rows (chunk mc), all 512 cols ----------------
        int idx = blk - 2304;
        int b = idx >> 3, mc = idx & 7;
        if (tid < 256)
            buf[tid] = rw[b * 2048 + (tid >> 6) * 512 + mc * 64 + (tid & 63)];
        __syncthreads();
        int n = tid;
        const float* lp = link + ((size_t)b * NN + mc * 64) * NN + n;
        float a0 = 0.f, a1 = 0.f, a2 = 0.f, a3 = 0.f;
#pragma unroll 8
        for (int m = 0; m < 64; m++) {
            float l = lp[(size_t)m * 512];
            a0 += l * buf[m];
            a1 += l * buf[64 + m];
            a2 += l * buf[128 + m];
            a3 += l * buf[192 + m];
        }
        size_t base = (((size_t)mc * 64 + b) * 4) * 512 + n;
        g_bwp[base]        = a0;
        g_bwp[base + 512]  = a1;
        g_bwp[base + 1024] = a2;
        g_bwp[base + 1536] = a3;
    }
}

// ============================================================
// 2) fused per-b: w_r mix + psi + rvec + pack inT
// ============================================================
__global__ void __launch_bounds__(512) k_mix(const float* __restrict__ mem,
                                             const float* __restrict__ x,
                                             const float* __restrict__ h,
                                             float* __restrict__ out) {
    int b = blockIdx.x, tid = threadIdx.x;
    __shared__ float swr[4][512];
    __shared__ float sred[512];
    __shared__ float srv[256];
    int n = tid;
    float psi = 1.f;
#pragma unroll
    for (int r = 0; r < 4; r++) {
        int o = (b * 4 + r) * 512 + n;
        float bwv = 0.f;
#pragma unroll
        for (int mc = 0; mc < 8; mc++)
            bwv += g_bwp[((size_t)(mc * 64 + b) * 4 + r) * 512 + n];
        float p0 = g_rpi[(b * 4 + r) * 3 + 0];
        float p1 = g_rpi[(b * 4 + r) * 3 + 1];
        float p2 = g_rpi[(b * 4 + r) * 3 + 2];
        float wr = p0 * bwv + p1 * g_cw[o] + p2 * g_fw[o];
        swr[r][n] = wr;
        out[OUT_WR + o] = wr;
        psi *= (1.f - wr);
    }
    g_psi[b * 512 + n] = psi;
    __syncthreads();

    int half = tid >> 8;
    int r = (tid >> 6) & 3;
    int v = tid & 63;
    const float* mp = mem + (size_t)b * NN * VV + v;
    float acc = 0.f;
#pragma unroll 4
    for (int nn = half * 256; nn < half * 256 + 256; nn++)
        acc += swr[r][nn] * mp[(size_t)nn * 64];
    sred[tid] = acc;
    __syncthreads();
    if (tid < 256) srv[tid] = sred[tid] + sred[tid + 256];
    __syncthreads();

    for (int k = tid; k < 896; k += 512) {
        float val;
        if (k < 128) val = x[b * 128 + k];
        else if (k < 384) val = srv[k - 128];
        else val = h[b * 512 + (k - 384)];
        g_inT[k * 64 + b] = val;
    }
}

// ============================================================
// 3) gates GEMM: (64b x 2048j), K=896 = 7 splits of 128; j-tile 32
//    grid (64, 7), block 256: tx=b(16,x4), ty=j(16,x2)
//    Wt padded to 34 (even) so float2 loads are 8B-aligned
// ============================================================
__global__ void __launch_bounds__(256) k_gates(const float* __restrict__ Wih,
                                               const float* __restrict__ Whh) {
    __shared__ __align__(16) float Wt[32][34];
    __shared__ __align__(16) float It[32][68];
    int tid = threadIdx.x;
    int ks = blockIdx.y;           // 0..6
    int koff = ks * 128;
    int j0 = blockIdx.x * 32;
    int tx = tid & 15, ty = tid >> 4;
    int jj = tid >> 3, kq = tid & 7;
    float acc[2][4];
#pragma unroll
    for (int i = 0; i < 2; i++)
#pragma unroll
        for (int j = 0; j < 4; j++) acc[i][j] = 0.f;

    for (int kst = 0; kst < 128; kst += 32) {
        int vk = koff + kst + kq * 4;
        const float* wp = (vk < 384) ? (Wih + (size_t)(j0 + jj) * 384 + vk)
                                     : (Whh + (size_t)(j0 + jj) * 512 + (vk - 384));
        float4 wv = *(const float4*)wp;
        Wt[kq * 4 + 0][jj] = wv.x;
        Wt[kq * 4 + 1][jj] = wv.y;
        Wt[kq * 4 + 2][jj] = wv.z;
        Wt[kq * 4 + 3][jj] = wv.w;
        *(float4*)&It[ty][tx * 4]      = *(const float4*)&g_inT[(koff + kst + ty) * 64 + tx * 4];
        *(float4*)&It[ty + 16][tx * 4] = *(const float4*)&g_inT[(koff + kst + ty + 16) * 64 + tx * 4];
        __syncthreads();
#pragma unroll
        for (int kk = 0; kk < 32; kk++) {
            float4 av = *(float4*)&It[kk][tx * 4];
            float2 wv2 = *(float2*)&Wt[kk][ty * 2];
            acc[0][0] += wv2.x * av.x; acc[0][1] += wv2.x * av.y; acc[0][2] += wv2.x * av.z; acc[0][3] += wv2.x * av.w;
            acc[1][0] += wv2.y * av.x; acc[1][1] += wv2.y * av.y; acc[1][2] += wv2.y * av.z; acc[1][3] += wv2.y * av.w;
        }
        __syncthreads();
    }
#pragma unroll
    for (int jq = 0; jq < 2; jq++)
#pragma unroll
        for (int bq = 0; bq < 4; bq++)
            g_gpart[(((size_t)ks * 64 + (tx * 4 + bq)) * 2048) + j0 + ty * 2 + jq] = acc[jq][bq];
}

// ============================================================
// 4) fused per-b: LSTM + output projections + full write path
// ============================================================
__global__ void __launch_bounds__(512) k_houtwall(
    const float* __restrict__ c, const float* __restrict__ bih, const float* __restrict__ bhh,
    const float* __restrict__ Ww, const float* __restrict__ bw_,
    const float* __restrict__ Wp, const float* __restrict__ bp,
    const float* __restrict__ Wv, const float* __restrict__ bv,
    const float* __restrict__ mem, const float* __restrict__ usage,
    const float* __restrict__ wwin, const float* __restrict__ prec,
    float* __restrict__ out) {
    int b = blockIdx.x, tid = threadIdx.x;
    __shared__ __align__(16) float sh[512];
    __shared__ __align__(16) float swo[200];
    __shared__ float salloc[512];
    __shared__ float sv[512];
    __shared__ float sp[512];
    __shared__ int si[512];
    __shared__ float red[16];
    __shared__ float part[2];
    __shared__ float s_beta, s_knorm, s_ga, s_gw, s_m, s_sum, s_ws;
    int lane = tid & 31, wid = tid >> 5;

    // ---- LSTM ----
    float gi = bih[tid] + bhh[tid];
    float gf = bih[512 + tid] + bhh[512 + tid];
    float gg = bih[1024 + tid] + bhh[1024 + tid];
    float go = bih[1536 + tid] + bhh[1536 + tid];
#pragma unroll
    for (int ks = 0; ks < 7; ks++) {
        const float* gp = g_gpart + ((size_t)(ks * 64 + b) * 2048);
        gi += gp[tid];
        gf += gp[512 + tid];
        gg += gp[1024 + tid];
        go += gp[1536 + tid];
    }
    float cn = sigf(gf) * c[b * 512 + tid] + sigf(gi) * tanhf(gg);
    float hn = sigf(go) * tanhf(cn);
    out[OUT_C + b * 512 + tid] = cn;
    out[OUT_H + b * 512 + tid] = hn;
    sh[tid] = hn;
    __syncthreads();

    // ---- projections (warp per row) ----
    for (int row = wid; row < 214; row += 16) {
        const float* wrow;
        float bias;
        if (row < 195)      { wrow = Ww + row * 512;         bias = bw_[row]; }
        else if (row < 213) { wrow = Wp + (row - 195) * 512; bias = bp[row - 195]; }
        else                { wrow = Wv;                     bias = bv[0]; }
        const float4* w4 = (const float4*)wrow;
        float acc = 0.f;
#pragma unroll
        for (int i = 0; i < 4; i++) {
            float4 wv = w4[lane + 32 * i];
            float4 hv = *(const float4*)&sh[(lane + 32 * i) * 4];
            acc += wv.x * hv.x + wv.y * hv.y + wv.z * hv.z + wv.w * hv.w;
        }
#pragma unroll
        for (int o = 16; o > 0; o >>= 1) acc += __shfl_down_sync(0xffffffffu, acc, o);
        if (lane == 0) {
            acc += bias;
            if (row < 195)      swo[row] = acc;
            else if (row < 213) out[OUT_LOGITS + b * 18 + (row - 195)] = acc;
            else                out[OUT_VALUE + b] = acc;
        }
    }
    __syncthreads();

    // ---- write prep ----
    if (tid < 64) {
        float kv = swo[tid];
        g_erase[b * 64 + tid] = sigf(swo[64 + tid]);
        g_add[b * 64 + tid] = tanhf(swo[128 + tid]);
        float s = kv * kv;
#pragma unroll
        for (int o = 16; o > 0; o >>= 1) s += __shfl_down_sync(0xffffffffu, s, o);
        if (lane == 0) part[tid >> 5] = s;
    }
    __syncthreads();
    if (tid == 0) {
        s_knorm = fmaxf(sqrtf(part[0] + part[1]), EPSF);
        s_beta = softplusf(swo[192]);
        s_ga = sigf(swo[193]);
        s_gw = sigf(swo[194]);
    }
    __syncthreads();

    // ---- write content sim (inline mem norm) ----
    const float4* mrow = (const float4*)(mem + ((size_t)b * NN + tid) * VV);
    float acc = 0.f, nrm = 0.f;
#pragma unroll
    for (int i = 0; i < 16; i++) {
        float4 m4 = mrow[i];
        acc += m4.x * swo[4 * i] + m4.y * swo[4 * i + 1] + m4.z * swo[4 * i + 2] + m4.w * swo[4 * i + 3];
        nrm += m4.x * m4.x + m4.y * m4.y + m4.z * m4.z + m4.w * m4.w;
    }
    float sim = s_beta * acc / (fmaxf(sqrtf(nrm), EPSF) * s_knorm);

    float v = sim;
#pragma unroll
    for (int o = 16; o > 0; o >>= 1) v = fmaxf(v, __shfl_down_sync(0xffffffffu, v, o));
    if (lane == 0) red[wid] = v;
    __syncthreads();
    if (tid == 0) {
        float m = red[0];
#pragma unroll
        for (int i = 1; i < 16; i++) m = fmaxf(m, red[i]);
        s_m = m;
    }
    __syncthreads();
    float e = expf(sim - s_m);
    v = e;
#pragma unroll
    for (int o = 16; o > 0; o >>= 1) v += __shfl_down_sync(0xffffffffu, v, o);
    if (lane == 0) red[wid] = v;
    __syncthreads();
    if (tid == 0) {
        float t = 0.f;
#pragma unroll
        for (int i = 0; i < 16; i++) t += red[i];
        s_sum = t;
    }
    __syncthreads();
    float cww = e / s_sum;

    // ---- allocation: bitonic sort + product scan + unsort ----
    sv[tid] = usage[b * 512 + tid];
    si[tid] = tid;
    __syncthreads();
    for (int k = 2; k <= 512; k <<= 1)
        for (int j = k >> 1; j > 0; j >>= 1) {
            int ixj = tid ^ j;
            if (ixj > tid) {
                float a = sv[tid], cc = sv[ixj];
                bool up = ((tid & k) == 0);
                if ((a > cc) == up) {
                    sv[tid] = cc; sv[ixj] = a;
                    int t = si[tid]; si[tid] = si[ixj]; si[ixj] = t;
                }
            }
            __syncthreads();
        }
    sp[tid] = sv[tid];
    __syncthreads();
    for (int off = 1; off < 512; off <<= 1) {
        float t = (tid >= off) ? sp[tid - off] : 1.f;
        __syncthreads();
        sp[tid] *= t;
        __syncthreads();
    }
    float excl = (tid == 0) ? 1.f : sp[tid - 1];
    salloc[si[tid]] = (1.f - sv[tid]) * excl;
    __syncthreads();

    // ---- write_w, ws, prec_new, usage_new ----
    float ww = s_gw * (s_ga * salloc[tid] + (1.f - s_ga) * cww);
    out[OUT_WW + b * 512 + tid] = ww;
    v = ww;
#pragma unroll
    for (int o = 16; o > 0; o >>= 1) v += __shfl_down_sync(0xffffffffu, v, o);
    if (lane == 0) red[wid] = v;
    __syncthreads();
    if (tid == 0) {
        float t = 0.f;
#pragma unroll
        for (int i = 0; i < 16; i++) t += red[i];
        s_ws = t;
    }
    __syncthreads();
    out[OUT_PREC + b * 512 + tid] = (1.f - s_ws) * prec[b * 512 + tid] + ww;
    float u = usage[b * 512 + tid], w0 = wwin[b * 512 + tid];
    out[OUT_USAGE + b * 512 + tid] = (u + w0 - u * w0) * g_psi[b * 512 + tid];
}

// ============================================================
// 5) fused memory + link update
// ============================================================
__global__ void k_memlink(const float* __restrict__ mem, const float* __restrict__ link,
                          const float* __restrict__ prec, float* __restrict__ out) {
    int bx = blockIdx.x;
    if (bx < 2048) {
        int gid = bx * 256 + threadIdx.x;
        int v4 = gid & 15, n = (gid >> 4) & 511, b = gid >> 13;
        float4 m = ((const float4*)mem)[gid];
        float ww = out[OUT_WW + b * 512 + n];
        float4 er = ((const float4*)g_erase)[b * 16 + v4];
        float4 ad = ((const float4*)g_add)[b * 16 + v4];
        float4 r;
        r.x = m.x * (1.f - ww * er.x) + ww * ad.x;
        r.y = m.y * (1.f - ww * er.y) + ww * ad.y;
        r.z = m.z * (1.f - ww * er.z) + ww * ad.z;
        r.w = m.w * (1.f - ww * er.w) + ww * ad.w;
        ((float4*)(out + OUT_MEM))[gid] = r;
    } else {
        int gid = (bx - 2048) * 256 + threadIdx.x;
        int mq = gid & 127, n = (gid >> 7) & 511, b = gid >> 16;
        float4 l = ((const float4*)link)[gid];
        float wn = out[OUT_WW + b * 512 + n];
        float4 wm = ((const float4*)(out + OUT_WW + b * 512))[mq];
        float4 p = ((const float4*)(prec + b * 512))[mq];
        float om = 1.f - wn;
        float4 r;
        r.x = om * (1.f - wm.x) * l.x + wn * p.x;
        r.y = om * (1.f - wm.y) * l.y + wn * p.y;
        r.z = om * (1.f - wm.z) * l.z + wn * p.z;
        r.w = om * (1.f - wm.w) * l.w + wn * p.w;
        int m0 = mq * 4;
        if (m0 == n)     r.x = 0.f;
        if (m0 + 1 == n) r.y = 0.f;
        if (m0 + 2 == n) r.z = 0.f;
        if (m0 + 3 == n) r.w = 0.f;
        ((float4*)(out + OUT_LINK))[gid] = r;
    }
}

extern "C" void kernel_launch(void* const* d_in, const int* in_sizes, int n_in,
                              void* d_out, int out_size) {
    const float* x             = (const float*)d_in[0];
    const float* h             = (const float*)d_in[1];
    const float* c             = (const float*)d_in[2];
    const float* memory        = (const float*)d_in[3];
    const float* read_weights  = (const float*)d_in[4];
    const float* write_weights = (const float*)d_in[5];
    const float* usage         = (const float*)d_in[6];
    const float* link          = (const float*)d_in[7];
    const float* prec          = (const float*)d_in[8];
    const float* W_ih          = (const float*)d_in[9];
    const float* W_hh          = (const float*)d_in[10];
    const float* b_ih          = (const float*)d_in[11];
    const float* b_hh          = (const float*)d_in[12];
    const float* W_read        = (const float*)d_in[13];
    const float* b_read        = (const float*)d_in[14];
    const float* W_write       = (const float*)d_in[15];
    const float* b_write       = (const float*)d_in[16];
    const float* W_pol         = (const float*)d_in[17];
    const float* b_pol         = (const float*)d_in[18];
    const float* W_val         = (const float*)d_in[19];
    const float* b_val         = (const float*)d_in[20];
    float* out = (float*)d_out;

    k_big<<<2816, 512>>>(memory, link, read_weights, h, W_read, b_read);
    k_mix<<<64, 512>>>(memory, x, h, out);
    k_gates<<<dim3(64, 7), 256>>>(W_ih, W_hh);
    k_houtwall<<<64, 512>>>(c, b_ih, b_hh, W_write, b_write, W_pol, b_pol, W_val, b_val,
                            memory, usage, write_weights, prec, out);
    k_memlink<<<18432, 256>>>(memory, link, prec, out);
}